// round 13
// baseline (speedup 1.0000x reference)
#include <cuda_runtime.h>
#include <cuda_fp16.h>
#include <math.h>
#include <stdint.h>

#define NP 100000
#define NA 50000
#define CDIM 128
#define CC (CDIM*CDIM)
#define NH 4
#define NPC (NP*CDIM)
#define EMAX 300000

#define PITCH 136                 // fp16 per row in staged images
#define PITCHB 272                // bytes
#define A_IMG 17408               // 64 rows * 272B
#define B_IMG 34816               // 128 rows * 272B
#define SLOT_U32 8704
#define NSLOT 22
#define CTAS_P ((NP+63)/64)
#define CTAS_A ((NA+63)/64)

// ---------------- scratch (device globals) -----------------------------------
__device__ float  g_x[2][(NP+NA)*CDIM];
__device__ __half g_q[(NP+NA)*CDIM];
__device__ __half g_krel[3][NPC];
__device__ __half g_vrel[3][NPC];
__device__ __half g_agg[(NP+NA)*CDIM];
__device__ float  g_Wk[2][3][CC];
__device__ float  g_Wv[2][3][CC];
__device__ float  g_bk[2][3][CDIM];
__device__ float  g_bv[2][3][CDIM];
__device__ uint32_t g_wpack[NSLOT][SLOT_U32];
__device__ int g_rowptr[3][NP+1];
__device__ int g_csrc[3][EMAX];
__device__ int g_cnt[NP];
__device__ int g_bsum[64];

// ---------------- small helpers ----------------------------------------------
__device__ __forceinline__ float gelu_f(float x) {
    return 0.5f * x * (1.0f + erff(x * 0.7071067811865476f));
}
__global__ void fill_i(int* __restrict__ p, int v, int n) {
    int i = blockIdx.x * blockDim.x + threadIdx.x;
    if (i < n) p[i] = v;
}
__global__ void hist_k(const int* __restrict__ dst, int* __restrict__ cnt, int E) {
    int i = blockIdx.x * blockDim.x + threadIdx.x;
    if (i < E) atomicAdd(&cnt[dst[i]], 1);
}
__global__ void scan1(const int* __restrict__ cnt, int* __restrict__ rp1,
                      int* __restrict__ bsum, int n) {
    __shared__ int sm[256];
    int base = blockIdx.x * 4096;
    int idx0 = base + threadIdx.x * 16;
    int v[16]; int t = 0;
#pragma unroll
    for (int j = 0; j < 16; j++) { int ix = idx0 + j; v[j] = (ix < n) ? cnt[ix] : 0; t += v[j]; }
    sm[threadIdx.x] = t;
    __syncthreads();
    for (int off = 1; off < 256; off <<= 1) {
        int x = 0;
        if ((int)threadIdx.x >= off) x = sm[threadIdx.x - off];
        __syncthreads();
        if ((int)threadIdx.x >= off) sm[threadIdx.x] += x;
        __syncthreads();
    }
    int run = sm[threadIdx.x] - t;
#pragma unroll
    for (int j = 0; j < 16; j++) { run += v[j]; int ix = idx0 + j; if (ix < n) rp1[ix] = run; }
    if (threadIdx.x == 255) bsum[blockIdx.x] = sm[255];
}
__global__ void scan2(int* __restrict__ bsum, int nb) {
    int tid = threadIdx.x;
    int orig = (tid < nb) ? bsum[tid] : 0;
    int v = orig;
    for (int off = 1; off < 32; off <<= 1) {
        int x = __shfl_up_sync(0xffffffffu, v, off);
        if (tid >= off) v += x;
    }
    if (tid < nb) bsum[tid] = v - orig;
}
__global__ void scan3(int* __restrict__ rowptr, const int* __restrict__ bsum,
                      int* __restrict__ cursor, int n) {
    int i = blockIdx.x * blockDim.x + threadIdx.x;
    if (i < n) {
        int val = rowptr[i + 1] + bsum[i >> 12];
        rowptr[i + 1] = val;
        if (i + 1 < n) cursor[i + 1] = val;
    }
    if (i == 0) { rowptr[0] = 0; cursor[0] = 0; }
}
__global__ void csr_fill(const int* __restrict__ src, const int* __restrict__ dst,
                         int* __restrict__ cursor, int* __restrict__ csrc, int E) {
    int i = blockIdx.x * blockDim.x + threadIdx.x;
    if (i >= E) return;
    int pos = atomicAdd(&cursor[dst[i]], 1);
    csrc[pos] = src[i];
}

// ---------------- PTX helpers -------------------------------------------------
__device__ __forceinline__ uint32_t smem_u32(const void* p) {
    uint32_t a;
    asm("{ .reg .u64 t; cvta.to.shared.u64 t, %1; cvt.u32.u64 %0, t; }" : "=r"(a) : "l"(p));
    return a;
}
__device__ __forceinline__ uint32_t pk_h2(__half a, __half b) {
    __half2 t = __halves2half2(a, b);
    return *reinterpret_cast<uint32_t*>(&t);
}
__device__ __forceinline__ void ldsm4(uint32_t* r, uint32_t addr) {
    asm volatile("ldmatrix.sync.aligned.m8n8.x4.shared.b16 {%0,%1,%2,%3}, [%4];"
        : "=r"(r[0]), "=r"(r[1]), "=r"(r[2]), "=r"(r[3]) : "r"(addr));
}
__device__ __forceinline__ void mma16816(float* c, const uint32_t* a, const uint32_t* b) {
    asm volatile("mma.sync.aligned.m16n8k16.row.col.f32.f16.f16.f32 "
        "{%0,%1,%2,%3}, {%4,%5,%6,%7}, {%8,%9}, {%0,%1,%2,%3};"
        : "+f"(c[0]), "+f"(c[1]), "+f"(c[2]), "+f"(c[3])
        : "r"(a[0]), "r"(a[1]), "r"(a[2]), "r"(a[3]), "r"(b[0]), "r"(b[1]));
}
__device__ __forceinline__ void cp16(uint32_t dst, const void* src) {
    asm volatile("cp.async.cg.shared.global [%0], [%1], 16;" :: "r"(dst), "l"(src));
}

// ---------------- weight packing: fp32 -> pitched fp16 -------------------------
struct PackSrc { const float* w[NSLOT]; int count; };
__global__ void pack_weights(PackSrc ps, uint32_t* dstbase) {
    int m = blockIdx.x;
    if (m >= ps.count) return;
    const float* W = ps.w[m];
    uint32_t* hi = dstbase + (size_t)m * SLOT_U32;
    int n = threadIdx.x;
    int k0 = blockIdx.y * 16;
    for (int k = k0; k < k0 + 16; k += 2) {
        hi[n * (PITCH / 2) + (k >> 1)] =
            pk_h2(__float2half_rn(W[k * 128 + n]), __float2half_rn(W[(k + 1) * 128 + n]));
    }
}

// ---------------- composite relation weights (both layers) ---------------------
__global__ void build_comp(const float* __restrict__ kw0, const float* __restrict__ kb0,
                           const float* __restrict__ vw0, const float* __restrict__ vb0,
                           const float* __restrict__ arel0, const float* __restrict__ mrel0,
                           float* __restrict__ Wk0, float* __restrict__ bk0,
                           float* __restrict__ Wv0, float* __restrict__ bv0) {
    int c = blockIdx.x, r = blockIdx.y, l = blockIdx.z, j = threadIdx.x;
    const float* kw = kw0 + (size_t)l * 2 * CC;
    const float* kb = kb0 + l * 2 * CDIM;
    const float* vw = vw0 + (size_t)l * 2 * CC;
    const float* vb = vb0 + l * 2 * CDIM;
    const float* arel = arel0 + (size_t)l * 3 * NH * 1024;
    const float* mrel = mrel0 + (size_t)l * 3 * NH * 1024;
    float* Wk = Wk0 + (size_t)l * 3 * CC;
    float* Wv = Wv0 + (size_t)l * 3 * CC;
    float* bk = bk0 + l * 3 * CDIM;
    float* bv = bv0 + l * 3 * CDIM;
    int st = (r == 1) ? 1 : 0;
    int h = j >> 5, e = j & 31;
    const float* kwp = kw + ((size_t)st * CDIM + c) * CDIM + h * 32;
    const float* vwp = vw + ((size_t)st * CDIM + c) * CDIM + h * 32;
    const float* ap  = arel + (size_t)(r * NH + h) * 1024 + e;
    const float* mp  = mrel + (size_t)(r * NH + h) * 1024 + e;
    float sk = 0.f, sv = 0.f;
#pragma unroll
    for (int d = 0; d < 32; d++) {
        sk += kwp[d] * ap[d * 32];
        sv += vwp[d] * mp[d * 32];
    }
    Wk[(size_t)r * CC + (size_t)c * CDIM + j] = sk;
    Wv[(size_t)r * CC + (size_t)c * CDIM + j] = sv;
    if (c == 0) {
        float bks = 0.f, bvs = 0.f;
        const float* kbp = kb + st * CDIM + h * 32;
        const float* vbp = vb + st * CDIM + h * 32;
#pragma unroll
        for (int d = 0; d < 32; d++) {
            bks += kbp[d] * ap[d * 32];
            bvs += vbp[d] * mp[d * 32];
        }
        bk[r * CDIM + j] = bks;
        bv[r * CDIM + j] = bvs;
    }
}

// ---------------- segmented chained mega-GEMM ----------------------------------
struct GemmSeg {
    const void*  A;
    const float* xold;
    const float* skipp;
    int M;
    int ntiles;
    int chain;
    int aHalf;
    const uint4* wp[6];
    const float* bias[6];
    void*        out[6];
    int          outHalf[6];
    int          eop[6];
};

#define SM_A     0
#define SM_B(b)  (A_IMG + (b)*B_IMG)
#define SM_NEED  (A_IMG + 2*B_IMG)

__device__ __forceinline__ void prefetch_B(uint32_t dstb, const uint4* src, int tid) {
#pragma unroll
    for (int i = 0; i < 8; i++) cp16(dstb + (uint32_t)(i * 256 + tid) * 16, src + i * 256 + tid);
    if (tid < 128) cp16(dstb + (uint32_t)(2048 + tid) * 16, src + 2048 + tid);
    asm volatile("cp.async.commit_group;" ::: "memory");
}

__global__ void __launch_bounds__(256, 2)
gemm_mega(GemmSeg P0, GemmSeg P1, int ctas0) {
    extern __shared__ char sm[];
    uint32_t sb = smem_u32(sm);
    int tid = threadIdx.x, lane = tid & 31, wid = tid >> 5;
    int wm = wid & 1, wn = wid >> 1;
    int bx = blockIdx.x;
    bool seg1 = bx >= ctas0;
    const GemmSeg& P = seg1 ? P1 : P0;
    int rowBase = (seg1 ? bx - ctas0 : bx) * 64;
    int M = P.M;

    prefetch_B(sb + SM_B(0), P.wp[0], tid);

    // ---- stage A ----
    if (P.aHalf) {
        const __half* Ah = (const __half*)P.A;
#pragma unroll
        for (int it = 0; it < 4; it++) {
            int f = it * 256 + tid;
            int m = f >> 4, c = f & 15;
            int row = rowBase + m;
            uint4 v = make_uint4(0, 0, 0, 0);
            if (row < M) v = *(const uint4*)(Ah + (size_t)row * CDIM + c * 8);
            *(uint4*)(sm + SM_A + m * PITCHB + c * 16) = v;
        }
    } else {
        const float* Af = (const float*)P.A;
#pragma unroll 4
        for (int it = 0; it < 8; it++) {
            int f = it * 256 + tid;
            int m = f >> 5, k = (f & 31) << 2;
            int row = rowBase + m;
            float4 v = make_float4(0.f, 0.f, 0.f, 0.f);
            if (row < M) v = *(const float4*)(Af + (size_t)row * CDIM + k);
            uint32_t off = (uint32_t)(m * PITCHB + k * 2);
            *(uint2*)(sm + SM_A + off) = make_uint2(
                pk_h2(__float2half_rn(v.x), __float2half_rn(v.y)),
                pk_h2(__float2half_rn(v.z), __float2half_rn(v.w)));
        }
    }

    int aRow = wm * 32 + (lane & 15);
    uint32_t aKoff = (lane & 16) ? 16u : 0u;
    uint32_t aBase = sb + SM_A + aRow * PITCHB + aKoff;
    int bN = wn * 32 + (lane & 7) + ((lane & 16) ? 8 : 0);
    uint32_t bKoff = (lane & 8) ? 16u : 0u;
    uint32_t bOff = bN * PITCHB + bKoff;

    float skv = 0.f;
    if (P.skipp) skv = 1.f / (1.f + expf(-*P.skipp));
    int g = lane >> 2, tg = lane & 3;
    int nt = P.ntiles;

    for (int b = 0; b < nt; b++) {
        if (b + 1 < nt) {
            prefetch_B(sb + SM_B((b + 1) & 1), P.wp[b + 1], tid);
            asm volatile("cp.async.wait_group 1;" ::: "memory");
        } else {
            asm volatile("cp.async.wait_group 0;" ::: "memory");
        }
        __syncthreads();

        float acc[2][4][4];
#pragma unroll
        for (int i = 0; i < 2; i++)
#pragma unroll
            for (int j = 0; j < 4; j++)
#pragma unroll
                for (int q = 0; q < 4; q++) acc[i][j][q] = 0.f;

        uint32_t aCur = aBase, bHi = sb + SM_B(b & 1) + bOff;
#pragma unroll
        for (int ks = 0; ks < 8; ks++) {
            uint32_t ah[2][4], bh[2][4];
            ldsm4(ah[0], aCur); ldsm4(ah[1], aCur + 16 * PITCHB);
            ldsm4(bh[0], bHi);  ldsm4(bh[1], bHi + 16 * PITCHB);
#pragma unroll
            for (int i = 0; i < 2; i++)
#pragma unroll
                for (int j = 0; j < 4; j++)
                    mma16816(acc[i][j], ah[i], &bh[j >> 1][(j & 1) * 2]);
            aCur += 32; bHi += 32;
        }
        __syncthreads();

        const float* bias = P.bias[b];
        int eop = P.eop[b];
        int oh = P.outHalf[b];
        bool chain0 = (b == 0) && P.chain;

        if (oh && eop == 0 && !chain0) {
            // ---- fast path: fp16 output, bias only; 4-lane shuffle transpose
            __half* outH = (__half*)P.out[b];
#pragma unroll
            for (int i = 0; i < 2; i++) {
#pragma unroll
                for (int half = 0; half < 2; half++) {
                    int row = rowBase + wm * 32 + i * 16 + half * 8 + g;
                    uint32_t pj[4];
#pragma unroll
                    for (int j = 0; j < 4; j++) {
                        int col = wn * 32 + j * 8 + tg * 2;
                        float v0 = acc[i][j][half * 2 + 0] + bias[col];
                        float v1 = acc[i][j][half * 2 + 1] + bias[col + 1];
                        pj[j] = pk_h2(__float2half_rn(v0), __float2half_rn(v1));
                    }
                    uint4 U;
                    uint32_t* Up = (uint32_t*)&U;
#pragma unroll
                    for (int r = 0; r < 4; r++) {
                        int src = (lane & ~3) | ((tg + r) & 3);
                        uint32_t sendv = pj[(tg + 4 - r) & 3];
                        Up[(tg + r) & 3] = __shfl_sync(0xffffffffu, sendv, src);
                    }
                    if (row < M)
                        *(uint4*)(outH + (size_t)row * CDIM + wn * 32 + tg * 8) = U;
                }
            }
        } else {
            // ---- general path (fp32 out / relu / skip-blend / chain) ----
            float* outF = (float*)P.out[b];
            __half* outH = (__half*)P.out[b];
#pragma unroll
            for (int i = 0; i < 2; i++) {
                int r0 = rowBase + wm * 32 + i * 16 + g;
#pragma unroll
                for (int j = 0; j < 4; j++) {
                    int col = wn * 32 + j * 8 + tg * 2;
                    float b0 = bias[col], b1 = bias[col + 1];
#pragma unroll
                    for (int half = 0; half < 2; half++) {
                        int row = r0 + half * 8;
                        if (row >= M) continue;
                        float v0 = acc[i][j][half * 2 + 0] + b0;
                        float v1 = acc[i][j][half * 2 + 1] + b1;
                        if (eop == 1) {
                            v0 = fmaxf(v0, 0.f); v1 = fmaxf(v1, 0.f);
                        } else if (eop == 2) {
                            float2 xo = *(const float2*)(P.xold + (size_t)row * CDIM + col);
                            v0 = skv * v0 + (1.f - skv) * xo.x;
                            v1 = skv * v1 + (1.f - skv) * xo.y;
                        }
                        if (oh) {
                            *(__half2*)(outH + (size_t)row * CDIM + col) = __floats2half2_rn(v0, v1);
                        } else {
                            *(float2*)(outF + (size_t)row * CDIM + col) = make_float2(v0, v1);
                        }
                        if (chain0) {
                            uint32_t off = (uint32_t)((row - rowBase) * PITCHB + col * 2);
                            *(__half2*)(sm + SM_A + off) = __floats2half2_rn(v0, v1);
                        }
                    }
                }
            }
        }
    }
}

// ---------------- merged edge gather: pair-unrolled, fp16 q/k/v ---------------
__device__ __forceinline__ float4 ld_half4(const __half* base, size_t off) {
    uint2 raw = *(const uint2*)(base + off);
    __half2* ph = (__half2*)&raw;
    float2 a = __half22float2(ph[0]);
    float2 b = __half22float2(ph[1]);
    return make_float4(a.x, a.y, b.x, b.y);
}
__device__ __forceinline__ float dot4(float4 a, float4 b) {
    return a.x * b.x + a.y * b.y + a.z * b.z + a.w * b.w;
}

__global__ void __launch_bounds__(256)
gather_all(const __half* __restrict__ q, __half* __restrict__ agg,
           const __half* __restrict__ krel, const __half* __restrict__ vrel,
           const int* __restrict__ rp0, const int* __restrict__ cs0,
           const int* __restrict__ rp1, const int* __restrict__ cs1,
           const int* __restrict__ rp2, const int* __restrict__ cs2,
           const float* __restrict__ prel) {
    int w = (blockIdx.x * blockDim.x + threadIdx.x) >> 5;
    if (w >= NP + NA) return;
    int lane = threadIdx.x & 31;
    int h = lane >> 3;
    size_t loff = (size_t)lane * 4;
    float4 qv = ld_half4(q, (size_t)w * CDIM + loff);
    float4 tot = make_float4(0.f, 0.f, 0.f, 0.f);
    int nrel, node;
    const int* rps[2]; const int* css[2]; int rr[2];
    if (w < NP) {
        nrel = 2; node = w;
        rps[0] = rp0; css[0] = cs0; rr[0] = 0;
        rps[1] = rp1; css[1] = cs1; rr[1] = 1;
    } else {
        nrel = 1; node = w - NP;
        rps[0] = rp2; css[0] = cs2; rr[0] = 2;
        rps[1] = rp2; css[1] = cs2; rr[1] = 2;
    }
    for (int rel = 0; rel < nrel; rel++) {
        const __half* kr = krel + (size_t)rr[rel] * NPC;
        const __half* vr = vrel + (size_t)rr[rel] * NPC;
        const int* rp = rps[rel];
        const int* cs = css[rel];
        float pscale = prel[rr[rel] * NH + h] * 0.17677669529663687f;
        int beg = rp[node], end = rp[node + 1];
        float m = -INFINITY, s = 0.f;
        float4 acc = make_float4(0.f, 0.f, 0.f, 0.f);

        float4 ka, va, kb2, vb2;
        if (beg < end) {
            int s0 = cs[beg];
            int s1 = (beg + 1 < end) ? cs[beg + 1] : s0;
            ka  = ld_half4(kr, (size_t)s0 * CDIM + loff);
            va  = ld_half4(vr, (size_t)s0 * CDIM + loff);
            kb2 = ld_half4(kr, (size_t)s1 * CDIM + loff);
            vb2 = ld_half4(vr, (size_t)s1 * CDIM + loff);
        }
        for (int e = beg; e < end; e += 2) {
            bool two = (e + 1 < end);
            float4 kc, vc, kd, vd;
            if (e + 2 < end) {
                int s0 = cs[e + 2];
                int s1 = (e + 3 < end) ? cs[e + 3] : s0;
                kc = ld_half4(kr, (size_t)s0 * CDIM + loff);
                vc = ld_half4(vr, (size_t)s0 * CDIM + loff);
                kd = ld_half4(kr, (size_t)s1 * CDIM + loff);
                vd = ld_half4(vr, (size_t)s1 * CDIM + loff);
            }
            float d0 = dot4(qv, ka);
            float d1 = dot4(qv, kb2);
            d0 += __shfl_xor_sync(0xffffffffu, d0, 1);
            d1 += __shfl_xor_sync(0xffffffffu, d1, 1);
            d0 += __shfl_xor_sync(0xffffffffu, d0, 2);
            d1 += __shfl_xor_sync(0xffffffffu, d1, 2);
            d0 += __shfl_xor_sync(0xffffffffu, d0, 4);
            d1 += __shfl_xor_sync(0xffffffffu, d1, 4);
            float a0 = d0 * pscale;
            float a1 = two ? d1 * pscale : -INFINITY;
            float mn = fmaxf(m, fmaxf(a0, a1));
            float sc = __expf(m - mn);
            float p0 = __expf(a0 - mn);
            float p1 = two ? __expf(a1 - mn) : 0.f;
            s = s * sc + p0 + p1;
            acc.x = acc.x * sc + p0 * va.x + p1 * vb2.x;
            acc.y = acc.y * sc + p0 * va.y + p1 * vb2.y;
            acc.z = acc.z * sc + p0 * va.z + p1 * vb2.z;
            acc.w = acc.w * sc + p0 * va.w + p1 * vb2.w;
            m = mn;
            ka = kc; va = vc; kb2 = kd; vb2 = vd;
        }
        float inv = 1.f / (s + 1e-16f);
        tot.x += acc.x * inv; tot.y += acc.y * inv;
        tot.z += acc.z * inv; tot.w += acc.w * inv;
    }
    uint2 outv;
    outv.x = pk_h2(__float2half_rn(gelu_f(tot.x)), __float2half_rn(gelu_f(tot.y)));
    outv.y = pk_h2(__float2half_rn(gelu_f(tot.z)), __float2half_rn(gelu_f(tot.w)));
    *(uint2*)(agg + (size_t)w * CDIM + loff) = outv;
}

// ---------------- host orchestration -------------------------------------------
extern "C" void kernel_launch(void* const* d_in, const int* in_sizes, int n_in,
                              void* d_out, int out_size) {
    const float* x_paper  = (const float*)d_in[0];
    const float* x_author = (const float*)d_in[1];
    const float* lin_w = (const float*)d_in[2];
    const float* lin_b = (const float*)d_in[3];
    const float* k_w = (const float*)d_in[4];
    const float* k_b = (const float*)d_in[5];
    const float* q_w = (const float*)d_in[6];
    const float* q_b = (const float*)d_in[7];
    const float* v_w = (const float*)d_in[8];
    const float* v_b = (const float*)d_in[9];
    const float* a_w = (const float*)d_in[10];
    const float* a_b = (const float*)d_in[11];
    const float* skip  = (const float*)d_in[12];
    const float* a_rel = (const float*)d_in[13];
    const float* m_rel = (const float*)d_in[14];
    const float* p_rel = (const float*)d_in[15];
    const int* srcs[3] = {(const int*)d_in[16], (const int*)d_in[18], (const int*)d_in[20]};
    const int* dsts[3] = {(const int*)d_in[17], (const int*)d_in[19], (const int*)d_in[21]};
    int E[3] = {in_sizes[16], in_sizes[18], in_sizes[20]};

    static cudaStream_t s1 = nullptr;
    static cudaEvent_t ev[2];
    if (!s1) {
        cudaStreamCreateWithFlags(&s1, cudaStreamNonBlocking);
        for (int i = 0; i < 2; i++) cudaEventCreateWithFlags(&ev[i], cudaEventDisableTiming);
        cudaFuncSetAttribute(gemm_mega, cudaFuncAttributeMaxDynamicSharedMemorySize, SM_NEED);
    }
    cudaStream_t s0 = 0;

    void* p;
    float *xb[2], *Wk, *Wv, *bk, *bv;
    __half *qb, *krel, *vrel, *agg;
    uint32_t* wpack;
    int *rowptr[3], *csrc[3], *cnt, *bsum;
    cudaGetSymbolAddress(&p, g_x);    xb[0] = (float*)p; xb[1] = xb[0] + (size_t)(NP + NA) * CDIM;
    cudaGetSymbolAddress(&p, g_q);    qb    = (__half*)p;
    cudaGetSymbolAddress(&p, g_krel); krel  = (__half*)p;
    cudaGetSymbolAddress(&p, g_vrel); vrel  = (__half*)p;
    cudaGetSymbolAddress(&p, g_agg);  agg   = (__half*)p;
    cudaGetSymbolAddress(&p, g_Wk);   Wk    = (float*)p;
    cudaGetSymbolAddress(&p, g_Wv);   Wv    = (float*)p;
    cudaGetSymbolAddress(&p, g_bk);   bk    = (float*)p;
    cudaGetSymbolAddress(&p, g_bv);   bv    = (float*)p;
    cudaGetSymbolAddress(&p, g_wpack);wpack = (uint32_t*)p;
    cudaGetSymbolAddress(&p, g_rowptr);
    for (int r = 0; r < 3; r++) rowptr[r] = (int*)p + (size_t)r * (NP + 1);
    cudaGetSymbolAddress(&p, g_csrc);
    for (int r = 0; r < 3; r++) csrc[r] = (int*)p + (size_t)r * EMAX;
    cudaGetSymbolAddress(&p, g_cnt);  cnt  = (int*)p;
    cudaGetSymbolAddress(&p, g_bsum); bsum = (int*)p;

    auto slot = [&](int s) { return (const uint4*)(wpack + (size_t)s * SLOT_U32); };
    auto setKV = [&](GemmSeg& G, int t, int sl, const float* bias, void* out) {
        G.wp[t] = slot(sl); G.bias[t] = bias; G.out[t] = out;
        G.outHalf[t] = 1; G.eop[t] = 0;
    };

    // ==== fork s1 from capture-origin stream ====
    cudaEventRecord(ev[0], s0);
    cudaStreamWaitEvent(s1, ev[0], 0);

    // launch order: build_comp(1), pack(2), fill_i(3), mega0(4)
    build_comp<<<dim3(CDIM, 3, 2), CDIM, 0, s0>>>(k_w, k_b, v_w, v_b, a_rel, m_rel,
                                                  Wk, bk, Wv, bv);
    {
        PackSrc ps{};
        for (int l = 0; l < 2; l++) {
            int base = l * 10;
            ps.w[base + 0] = q_w + (size_t)(l * 2 + 0) * CC;
            ps.w[base + 1] = q_w + (size_t)(l * 2 + 1) * CC;
            ps.w[base + 2] = Wk + (size_t)(l * 3 + 0) * CC;
            ps.w[base + 3] = Wv + (size_t)(l * 3 + 0) * CC;
            ps.w[base + 4] = Wk + (size_t)(l * 3 + 2) * CC;
            ps.w[base + 5] = Wv + (size_t)(l * 3 + 2) * CC;
            ps.w[base + 6] = Wk + (size_t)(l * 3 + 1) * CC;
            ps.w[base + 7] = Wv + (size_t)(l * 3 + 1) * CC;
            ps.w[base + 8] = a_w + (size_t)(l * 2 + 0) * CC;
            ps.w[base + 9] = a_w + (size_t)(l * 2 + 1) * CC;
        }
        ps.w[20] = lin_w; ps.w[21] = lin_w + CC;
        ps.count = NSLOT;
        pack_weights<<<dim3(NSLOT, 8), 128, 0, s0>>>(ps, wpack);
    }
    fill_i<<<(NP + 255) / 256, 256, 0, s1>>>(cnt, 0, NP);

    // megaGEMM0: wrapper(relu) chained into L0 q/krel/vrel
    {
        GemmSeg P{}, Q{};
        const float* bk0 = bk;
        const float* bv0 = bv;
        P.A = x_paper; P.xold = nullptr; P.skipp = nullptr;
        P.M = NP; P.ntiles = 6; P.chain = 1; P.aHalf = 0;
        P.wp[0] = slot(20); P.bias[0] = lin_b; P.out[0] = xb[0]; P.outHalf[0] = 0; P.eop[0] = 1;
        setKV(P, 1, 0, q_b, qb);
        setKV(P, 2, 2, bk0,            krel);
        setKV(P, 3, 3, bv0,            vrel);
        setKV(P, 4, 4, bk0 + 2 * CDIM, krel + 2 * (size_t)NPC);
        setKV(P, 5, 5, bv0 + 2 * CDIM, vrel + 2 * (size_t)NPC);
        Q.A = x_author; Q.xold = nullptr; Q.skipp = nullptr;
        Q.M = NA; Q.ntiles = 4; Q.chain = 1; Q.aHalf = 0;
        Q.wp[0] = slot(21); Q.bias[0] = lin_b + CDIM; Q.out[0] = xb[0] + NPC; Q.outHalf[0] = 0; Q.eop[0] = 1;
        setKV(Q, 1, 1, q_b + CDIM, qb + NPC);
        setKV(Q, 2, 6, bk0 + CDIM, krel + (size_t)NPC);
        setKV(Q, 3, 7, bv0 + CDIM, vrel + (size_t)NPC);
        gemm_mega<<<CTAS_P + CTAS_A, 256, SM_NEED, s0>>>(P, Q, CTAS_P);
    }

    // rest of CSR build on s1 (concurrent with mega0)
    {
        int r = 0;
        int Nd = NP;
        hist_k<<<(E[r] + 255) / 256, 256, 0, s1>>>(dsts[r], cnt, E[r]);
        int nb = (Nd + 4095) / 4096;
        scan1<<<nb, 256, 0, s1>>>(cnt, rowptr[r] + 1, bsum, Nd);
        scan2<<<1, 32, 0, s1>>>(bsum, nb);
        scan3<<<(Nd + 255) / 256, 256, 0, s1>>>(rowptr[r], bsum, cnt, Nd);
        csr_fill<<<(E[r] + 255) / 256, 256, 0, s1>>>(srcs[r], dsts[r], cnt, csrc[r], E[r]);
    }
    for (int r = 1; r < 3; r++) {
        int Nd = (r == 2) ? NA : NP;
        fill_i<<<(Nd + 255) / 256, 256, 0, s1>>>(cnt, 0, Nd);
        hist_k<<<(E[r] + 255) / 256, 256, 0, s1>>>(dsts[r], cnt, E[r]);
        int nb = (Nd + 4095) / 4096;
        scan1<<<nb, 256, 0, s1>>>(cnt, rowptr[r] + 1, bsum, Nd);
        scan2<<<1, 32, 0, s1>>>(bsum, nb);
        scan3<<<(Nd + 255) / 256, 256, 0, s1>>>(rowptr[r], bsum, cnt, Nd);
        csr_fill<<<(E[r] + 255) / 256, 256, 0, s1>>>(srcs[r], dsts[r], cnt, csrc[r], E[r]);
    }
    cudaEventRecord(ev[1], s1);
    cudaStreamWaitEvent(s0, ev[1], 0);

    // gather L0
    gather_all<<<((NP + NA) * 32 + 255) / 256, 256, 0, s0>>>(
        qb, agg, krel, vrel,
        rowptr[0], csrc[0], rowptr[1], csrc[1], rowptr[2], csrc[2],
        p_rel + 0 * 3 * NH);

    // megaGEMM1
    {
        GemmSeg P{}, Q{};
        const float* bk1 = bk + 3 * CDIM;
        const float* bv1 = bv + 3 * CDIM;
        P.A = agg; P.xold = xb[0]; P.skipp = skip + 0;
        P.M = NP; P.ntiles = 6; P.chain = 1; P.aHalf = 1;
        P.wp[0] = slot(8);  P.bias[0] = a_b; P.out[0] = xb[1]; P.outHalf[0] = 0; P.eop[0] = 2;
        setKV(P, 1, 10, q_b + 2 * CDIM, qb);
        setKV(P, 2, 12, bk1,            krel);
        setKV(P, 3, 13, bv1,            vrel);
        setKV(P, 4, 14, bk1 + 2 * CDIM, krel + 2 * (size_t)NPC);
        setKV(P, 5, 15, bv1 + 2 * CDIM, vrel + 2 * (size_t)NPC);
        Q.A = agg + NPC; Q.xold = xb[0] + NPC; Q.skipp = skip + 1;
        Q.M = NA; Q.ntiles = 4; Q.chain = 1; Q.aHalf = 1;
        Q.wp[0] = slot(9); Q.bias[0] = a_b + CDIM; Q.out[0] = xb[1] + NPC; Q.outHalf[0] = 0; Q.eop[0] = 2;
        setKV(Q, 1, 11, q_b + 3 * CDIM, qb + NPC);
        setKV(Q, 2, 16, bk1 + CDIM, krel + (size_t)NPC);
        setKV(Q, 3, 17, bv1 + CDIM, vrel + (size_t)NPC);
        gemm_mega<<<CTAS_P + CTAS_A, 256, SM_NEED, s0>>>(P, Q, CTAS_P);
    }

    // gather L1
    gather_all<<<((NP + NA) * 32 + 255) / 256, 256, 0, s0>>>(
        qb, agg, krel, vrel,
        rowptr[0], csrc[0], rowptr[1], csrc[1], rowptr[2], csrc[2],
        p_rel + 1 * 3 * NH);

    // final: L1 out-proj -> d_out
    {
        GemmSeg P{}, Q{};
        P.A = agg; P.xold = xb[1]; P.skipp = skip + 2;
        P.M = NP; P.ntiles = 1; P.chain = 0; P.aHalf = 1;
        P.wp[0] = slot(18); P.bias[0] = a_b + 2 * CDIM; P.out[0] = (float*)d_out;
        P.outHalf[0] = 0; P.eop[0] = 2;
        Q.A = agg + NPC; Q.xold = xb[1] + NPC; Q.skipp = skip + 3;
        Q.M = NA; Q.ntiles = 1; Q.chain = 0; Q.aHalf = 1;
        Q.wp[0] = slot(19); Q.bias[0] = a_b + 3 * CDIM; Q.out[0] = (float*)d_out + NPC;
        Q.outHalf[0] = 0; Q.eop[0] = 2;
        gemm_mega<<<CTAS_P + CTAS_A, 256, SM_NEED, s0>>>(P, Q, CTAS_P);
    }
}

// round 14
// speedup vs baseline: 1.2626x; 1.2626x over previous
#include <cuda_runtime.h>
#include <cuda_fp16.h>
#include <math.h>
#include <stdint.h>

#define NP 100000
#define NA 50000
#define CDIM 128
#define CC (CDIM*CDIM)
#define NH 4
#define NPC (NP*CDIM)
#define EMAX 300000

#define PITCH 136                 // fp16 per row in staged images
#define PITCHB 272                // bytes
#define A_IMG 17408               // 64 rows * 272B
#define B_IMG 34816               // 128 rows * 272B
#define SLOT_U32 8704
#define NSLOT 22
#define CTAS_P ((NP+63)/64)
#define CTAS_A ((NA+63)/64)

// ---------------- scratch (device globals) -----------------------------------
__device__ float  g_x[2][(NP+NA)*CDIM];
__device__ __half g_q[(NP+NA)*CDIM];
__device__ __half g_krel[3][NPC];
__device__ __half g_vrel[3][NPC];
__device__ __half g_agg[(NP+NA)*CDIM];
__device__ float  g_Wk[2][3][CC];
__device__ float  g_Wv[2][3][CC];
__device__ float  g_bk[2][3][CDIM];
__device__ float  g_bv[2][3][CDIM];
__device__ uint32_t g_wpack[NSLOT][SLOT_U32];
__device__ int g_rowptr[3][NP+1];
__device__ int g_csrc[3][EMAX];
__device__ int g_cnt[NP];
__device__ int g_bsum[64];

// ---------------- small helpers ----------------------------------------------
__device__ __forceinline__ float gelu_f(float x) {
    return 0.5f * x * (1.0f + erff(x * 0.7071067811865476f));
}
__global__ void fill_i(int* __restrict__ p, int v, int n) {
    int i = blockIdx.x * blockDim.x + threadIdx.x;
    if (i < n) p[i] = v;
}
__global__ void hist_k(const int* __restrict__ dst, int* __restrict__ cnt, int E) {
    int i = blockIdx.x * blockDim.x + threadIdx.x;
    if (i < E) atomicAdd(&cnt[dst[i]], 1);
}
__global__ void scan1(const int* __restrict__ cnt, int* __restrict__ rp1,
                      int* __restrict__ bsum, int n) {
    __shared__ int sm[256];
    int base = blockIdx.x * 4096;
    int idx0 = base + threadIdx.x * 16;
    int v[16]; int t = 0;
#pragma unroll
    for (int j = 0; j < 16; j++) { int ix = idx0 + j; v[j] = (ix < n) ? cnt[ix] : 0; t += v[j]; }
    sm[threadIdx.x] = t;
    __syncthreads();
    for (int off = 1; off < 256; off <<= 1) {
        int x = 0;
        if ((int)threadIdx.x >= off) x = sm[threadIdx.x - off];
        __syncthreads();
        if ((int)threadIdx.x >= off) sm[threadIdx.x] += x;
        __syncthreads();
    }
    int run = sm[threadIdx.x] - t;
#pragma unroll
    for (int j = 0; j < 16; j++) { run += v[j]; int ix = idx0 + j; if (ix < n) rp1[ix] = run; }
    if (threadIdx.x == 255) bsum[blockIdx.x] = sm[255];
}
__global__ void scan2(int* __restrict__ bsum, int nb) {
    int tid = threadIdx.x;
    int orig = (tid < nb) ? bsum[tid] : 0;
    int v = orig;
    for (int off = 1; off < 32; off <<= 1) {
        int x = __shfl_up_sync(0xffffffffu, v, off);
        if (tid >= off) v += x;
    }
    if (tid < nb) bsum[tid] = v - orig;
}
__global__ void scan3(int* __restrict__ rowptr, const int* __restrict__ bsum,
                      int* __restrict__ cursor, int n) {
    int i = blockIdx.x * blockDim.x + threadIdx.x;
    if (i < n) {
        int val = rowptr[i + 1] + bsum[i >> 12];
        rowptr[i + 1] = val;
        if (i + 1 < n) cursor[i + 1] = val;
    }
    if (i == 0) { rowptr[0] = 0; cursor[0] = 0; }
}
__global__ void csr_fill(const int* __restrict__ src, const int* __restrict__ dst,
                         int* __restrict__ cursor, int* __restrict__ csrc, int E) {
    int i = blockIdx.x * blockDim.x + threadIdx.x;
    if (i >= E) return;
    int pos = atomicAdd(&cursor[dst[i]], 1);
    csrc[pos] = src[i];
}

// ---------------- PTX helpers -------------------------------------------------
__device__ __forceinline__ uint32_t smem_u32(const void* p) {
    uint32_t a;
    asm("{ .reg .u64 t; cvta.to.shared.u64 t, %1; cvt.u32.u64 %0, t; }" : "=r"(a) : "l"(p));
    return a;
}
__device__ __forceinline__ uint32_t pk_h2(__half a, __half b) {
    __half2 t = __halves2half2(a, b);
    return *reinterpret_cast<uint32_t*>(&t);
}
__device__ __forceinline__ void ldsm4(uint32_t* r, uint32_t addr) {
    asm volatile("ldmatrix.sync.aligned.m8n8.x4.shared.b16 {%0,%1,%2,%3}, [%4];"
        : "=r"(r[0]), "=r"(r[1]), "=r"(r[2]), "=r"(r[3]) : "r"(addr));
}
__device__ __forceinline__ void mma16816(float* c, const uint32_t* a, const uint32_t* b) {
    asm volatile("mma.sync.aligned.m16n8k16.row.col.f32.f16.f16.f32 "
        "{%0,%1,%2,%3}, {%4,%5,%6,%7}, {%8,%9}, {%0,%1,%2,%3};"
        : "+f"(c[0]), "+f"(c[1]), "+f"(c[2]), "+f"(c[3])
        : "r"(a[0]), "r"(a[1]), "r"(a[2]), "r"(a[3]), "r"(b[0]), "r"(b[1]));
}
__device__ __forceinline__ void cp16(uint32_t dst, const void* src) {
    asm volatile("cp.async.cg.shared.global [%0], [%1], 16;" :: "r"(dst), "l"(src));
}

// ---------------- weight packing: fp32 -> pitched fp16 -------------------------
struct PackSrc { const float* w[NSLOT]; int count; };
__global__ void pack_weights(PackSrc ps, uint32_t* dstbase) {
    int m = blockIdx.x;
    if (m >= ps.count) return;
    const float* W = ps.w[m];
    uint32_t* hi = dstbase + (size_t)m * SLOT_U32;
    int n = threadIdx.x;
    int k0 = blockIdx.y * 16;
    for (int k = k0; k < k0 + 16; k += 2) {
        hi[n * (PITCH / 2) + (k >> 1)] =
            pk_h2(__float2half_rn(W[k * 128 + n]), __float2half_rn(W[(k + 1) * 128 + n]));
    }
}

// ---------------- composite relation weights (both layers) ---------------------
__global__ void build_comp(const float* __restrict__ kw0, const float* __restrict__ kb0,
                           const float* __restrict__ vw0, const float* __restrict__ vb0,
                           const float* __restrict__ arel0, const float* __restrict__ mrel0,
                           float* __restrict__ Wk0, float* __restrict__ bk0,
                           float* __restrict__ Wv0, float* __restrict__ bv0) {
    int c = blockIdx.x, r = blockIdx.y, l = blockIdx.z, j = threadIdx.x;
    const float* kw = kw0 + (size_t)l * 2 * CC;
    const float* kb = kb0 + l * 2 * CDIM;
    const float* vw = vw0 + (size_t)l * 2 * CC;
    const float* vb = vb0 + l * 2 * CDIM;
    const float* arel = arel0 + (size_t)l * 3 * NH * 1024;
    const float* mrel = mrel0 + (size_t)l * 3 * NH * 1024;
    float* Wk = Wk0 + (size_t)l * 3 * CC;
    float* Wv = Wv0 + (size_t)l * 3 * CC;
    float* bk = bk0 + l * 3 * CDIM;
    float* bv = bv0 + l * 3 * CDIM;
    int st = (r == 1) ? 1 : 0;
    int h = j >> 5, e = j & 31;
    const float* kwp = kw + ((size_t)st * CDIM + c) * CDIM + h * 32;
    const float* vwp = vw + ((size_t)st * CDIM + c) * CDIM + h * 32;
    const float* ap  = arel + (size_t)(r * NH + h) * 1024 + e;
    const float* mp  = mrel + (size_t)(r * NH + h) * 1024 + e;
    float sk = 0.f, sv = 0.f;
#pragma unroll
    for (int d = 0; d < 32; d++) {
        sk += kwp[d] * ap[d * 32];
        sv += vwp[d] * mp[d * 32];
    }
    Wk[(size_t)r * CC + (size_t)c * CDIM + j] = sk;
    Wv[(size_t)r * CC + (size_t)c * CDIM + j] = sv;
    if (c == 0) {
        float bks = 0.f, bvs = 0.f;
        const float* kbp = kb + st * CDIM + h * 32;
        const float* vbp = vb + st * CDIM + h * 32;
#pragma unroll
        for (int d = 0; d < 32; d++) {
            bks += kbp[d] * ap[d * 32];
            bvs += vbp[d] * mp[d * 32];
        }
        bk[r * CDIM + j] = bks;
        bv[r * CDIM + j] = bvs;
    }
}

// ---------------- segmented chained mega-GEMM ----------------------------------
struct GemmSeg {
    const void*  A;
    const float* xold;
    const float* skipp;
    int M;
    int ntiles;
    int chain;
    int aHalf;
    const uint4* wp[6];
    const float* bias[6];
    void*        out[6];
    int          outHalf[6];
    int          eop[6];
};

#define SM_A     0
#define SM_B(b)  (A_IMG + (b)*B_IMG)
#define SM_NEED  (A_IMG + 2*B_IMG)

__device__ __forceinline__ void prefetch_B(uint32_t dstb, const uint4* src, int tid) {
#pragma unroll
    for (int i = 0; i < 8; i++) cp16(dstb + (uint32_t)(i * 256 + tid) * 16, src + i * 256 + tid);
    if (tid < 128) cp16(dstb + (uint32_t)(2048 + tid) * 16, src + 2048 + tid);
    asm volatile("cp.async.commit_group;" ::: "memory");
}

__global__ void __launch_bounds__(256, 2)
gemm_mega(GemmSeg P0, GemmSeg P1, int ctas0) {
    extern __shared__ char sm[];
    uint32_t sb = smem_u32(sm);
    int tid = threadIdx.x, lane = tid & 31, wid = tid >> 5;
    int wm = wid & 1, wn = wid >> 1;
    int bx = blockIdx.x;
    bool seg1 = bx >= ctas0;
    const GemmSeg& P = seg1 ? P1 : P0;
    int rowBase = (seg1 ? bx - ctas0 : bx) * 64;
    int M = P.M;

    prefetch_B(sb + SM_B(0), P.wp[0], tid);

    // ---- stage A ----
    if (P.aHalf) {
        const __half* Ah = (const __half*)P.A;
#pragma unroll
        for (int it = 0; it < 4; it++) {
            int f = it * 256 + tid;
            int m = f >> 4, c = f & 15;
            int row = rowBase + m;
            uint4 v = make_uint4(0, 0, 0, 0);
            if (row < M) v = *(const uint4*)(Ah + (size_t)row * CDIM + c * 8);
            *(uint4*)(sm + SM_A + m * PITCHB + c * 16) = v;
        }
    } else {
        const float* Af = (const float*)P.A;
#pragma unroll 4
        for (int it = 0; it < 8; it++) {
            int f = it * 256 + tid;
            int m = f >> 5, k = (f & 31) << 2;
            int row = rowBase + m;
            float4 v = make_float4(0.f, 0.f, 0.f, 0.f);
            if (row < M) v = *(const float4*)(Af + (size_t)row * CDIM + k);
            uint32_t off = (uint32_t)(m * PITCHB + k * 2);
            *(uint2*)(sm + SM_A + off) = make_uint2(
                pk_h2(__float2half_rn(v.x), __float2half_rn(v.y)),
                pk_h2(__float2half_rn(v.z), __float2half_rn(v.w)));
        }
    }

    int aRow = wm * 32 + (lane & 15);
    uint32_t aKoff = (lane & 16) ? 16u : 0u;
    uint32_t aBase = sb + SM_A + aRow * PITCHB + aKoff;
    int bN = wn * 32 + (lane & 7) + ((lane & 16) ? 8 : 0);
    uint32_t bKoff = (lane & 8) ? 16u : 0u;
    uint32_t bOff = bN * PITCHB + bKoff;

    float skv = 0.f;
    if (P.skipp) skv = 1.f / (1.f + expf(-*P.skipp));
    int g = lane >> 2, tg = lane & 3;
    int nt = P.ntiles;

    for (int b = 0; b < nt; b++) {
        if (b + 1 < nt) {
            prefetch_B(sb + SM_B((b + 1) & 1), P.wp[b + 1], tid);
            asm volatile("cp.async.wait_group 1;" ::: "memory");
        } else {
            asm volatile("cp.async.wait_group 0;" ::: "memory");
        }
        __syncthreads();

        float acc[2][4][4];
#pragma unroll
        for (int i = 0; i < 2; i++)
#pragma unroll
            for (int j = 0; j < 4; j++)
#pragma unroll
                for (int q = 0; q < 4; q++) acc[i][j][q] = 0.f;

        uint32_t aCur = aBase, bHi = sb + SM_B(b & 1) + bOff;
#pragma unroll
        for (int ks = 0; ks < 8; ks++) {
            uint32_t ah[2][4], bh[2][4];
            ldsm4(ah[0], aCur); ldsm4(ah[1], aCur + 16 * PITCHB);
            ldsm4(bh[0], bHi);  ldsm4(bh[1], bHi + 16 * PITCHB);
#pragma unroll
            for (int i = 0; i < 2; i++)
#pragma unroll
                for (int j = 0; j < 4; j++)
                    mma16816(acc[i][j], ah[i], &bh[j >> 1][(j & 1) * 2]);
            aCur += 32; bHi += 32;
        }
        __syncthreads();   // MMA reads of B(b&1) complete -> reusable as scratch

        const float* bias = P.bias[b];
        int eop = P.eop[b];
        int oh = P.outHalf[b];
        bool chain0 = (b == 0) && P.chain;

        if (oh && eop == 0 && !chain0) {
            // ---- fast path: transpose via dead B buffer, coalesced stores ----
            __half* outH = (__half*)P.out[b];
            char* scr = sm + SM_B(b & 1);
            // scatter into scratch (272B row stride -> conflict-free STS)
#pragma unroll
            for (int i = 0; i < 2; i++)
#pragma unroll
                for (int j = 0; j < 4; j++) {
                    int col = wn * 32 + j * 8 + tg * 2;
                    float b0 = bias[col], b1 = bias[col + 1];
#pragma unroll
                    for (int half = 0; half < 2; half++) {
                        int rl = wm * 32 + i * 16 + half * 8 + g;
                        float v0 = acc[i][j][half * 2 + 0] + b0;
                        float v1 = acc[i][j][half * 2 + 1] + b1;
                        *(uint32_t*)(scr + rl * PITCHB + col * 2) =
                            pk_h2(__float2half_rn(v0), __float2half_rn(v1));
                    }
                }
            __syncthreads();
            // coalesced copy: 64 rows x 256B payload
#pragma unroll
            for (int it = 0; it < 4; it++) {
                int f = it * 256 + tid;
                int m = f >> 4, c = f & 15;
                int row = rowBase + m;
                uint4 v = *(uint4*)(scr + m * PITCHB + c * 16);
                if (row < M)
                    *(uint4*)(outH + (size_t)row * CDIM + c * 8) = v;
            }
            __syncthreads();   // scratch reads done before iter b+1 prefetch reuses it
        } else {
            // ---- general path (fp32 out / relu / skip-blend / chain) ----
            float* outF = (float*)P.out[b];
            __half* outH = (__half*)P.out[b];
#pragma unroll
            for (int i = 0; i < 2; i++) {
                int r0 = rowBase + wm * 32 + i * 16 + g;
#pragma unroll
                for (int j = 0; j < 4; j++) {
                    int col = wn * 32 + j * 8 + tg * 2;
                    float b0 = bias[col], b1 = bias[col + 1];
#pragma unroll
                    for (int half = 0; half < 2; half++) {
                        int row = r0 + half * 8;
                        if (row >= M) continue;
                        float v0 = acc[i][j][half * 2 + 0] + b0;
                        float v1 = acc[i][j][half * 2 + 1] + b1;
                        if (eop == 1) {
                            v0 = fmaxf(v0, 0.f); v1 = fmaxf(v1, 0.f);
                        } else if (eop == 2) {
                            float2 xo = *(const float2*)(P.xold + (size_t)row * CDIM + col);
                            v0 = skv * v0 + (1.f - skv) * xo.x;
                            v1 = skv * v1 + (1.f - skv) * xo.y;
                        }
                        if (oh) {
                            *(__half2*)(outH + (size_t)row * CDIM + col) = __floats2half2_rn(v0, v1);
                        } else {
                            *(float2*)(outF + (size_t)row * CDIM + col) = make_float2(v0, v1);
                        }
                        if (chain0) {
                            uint32_t off = (uint32_t)((row - rowBase) * PITCHB + col * 2);
                            *(__half2*)(sm + SM_A + off) = __floats2half2_rn(v0, v1);
                        }
                    }
                }
            }
        }
    }
}

// ---------------- merged edge gather: pair-unrolled, fp16 q/k/v ---------------
__device__ __forceinline__ float4 ld_half4(const __half* base, size_t off) {
    uint2 raw = *(const uint2*)(base + off);
    __half2* ph = (__half2*)&raw;
    float2 a = __half22float2(ph[0]);
    float2 b = __half22float2(ph[1]);
    return make_float4(a.x, a.y, b.x, b.y);
}
__device__ __forceinline__ float dot4(float4 a, float4 b) {
    return a.x * b.x + a.y * b.y + a.z * b.z + a.w * b.w;
}

__global__ void __launch_bounds__(256)
gather_all(const __half* __restrict__ q, __half* __restrict__ agg,
           const __half* __restrict__ krel, const __half* __restrict__ vrel,
           const int* __restrict__ rp0, const int* __restrict__ cs0,
           const int* __restrict__ rp1, const int* __restrict__ cs1,
           const int* __restrict__ rp2, const int* __restrict__ cs2,
           const float* __restrict__ prel) {
    int w = (blockIdx.x * blockDim.x + threadIdx.x) >> 5;
    if (w >= NP + NA) return;
    int lane = threadIdx.x & 31;
    int h = lane >> 3;
    size_t loff = (size_t)lane * 4;
    float4 qv = ld_half4(q, (size_t)w * CDIM + loff);
    float4 tot = make_float4(0.f, 0.f, 0.f, 0.f);
    int nrel, node;
    const int* rps[2]; const int* css[2]; int rr[2];
    if (w < NP) {
        nrel = 2; node = w;
        rps[0] = rp0; css[0] = cs0; rr[0] = 0;
        rps[1] = rp1; css[1] = cs1; rr[1] = 1;
    } else {
        nrel = 1; node = w - NP;
        rps[0] = rp2; css[0] = cs2; rr[0] = 2;
        rps[1] = rp2; css[1] = cs2; rr[1] = 2;
    }
    for (int rel = 0; rel < nrel; rel++) {
        const __half* kr = krel + (size_t)rr[rel] * NPC;
        const __half* vr = vrel + (size_t)rr[rel] * NPC;
        const int* rp = rps[rel];
        const int* cs = css[rel];
        float pscale = prel[rr[rel] * NH + h] * 0.17677669529663687f;
        int beg = rp[node], end = rp[node + 1];
        float m = -INFINITY, s = 0.f;
        float4 acc = make_float4(0.f, 0.f, 0.f, 0.f);

        float4 ka, va, kb2, vb2;
        if (beg < end) {
            int s0 = cs[beg];
            int s1 = (beg + 1 < end) ? cs[beg + 1] : s0;
            ka  = ld_half4(kr, (size_t)s0 * CDIM + loff);
            va  = ld_half4(vr, (size_t)s0 * CDIM + loff);
            kb2 = ld_half4(kr, (size_t)s1 * CDIM + loff);
            vb2 = ld_half4(vr, (size_t)s1 * CDIM + loff);
        }
        for (int e = beg; e < end; e += 2) {
            bool two = (e + 1 < end);
            float4 kc, vc, kd, vd;
            if (e + 2 < end) {
                int s0 = cs[e + 2];
                int s1 = (e + 3 < end) ? cs[e + 3] : s0;
                kc = ld_half4(kr, (size_t)s0 * CDIM + loff);
                vc = ld_half4(vr, (size_t)s0 * CDIM + loff);
                kd = ld_half4(kr, (size_t)s1 * CDIM + loff);
                vd = ld_half4(vr, (size_t)s1 * CDIM + loff);
            }
            float d0 = dot4(qv, ka);
            float d1 = dot4(qv, kb2);
            d0 += __shfl_xor_sync(0xffffffffu, d0, 1);
            d1 += __shfl_xor_sync(0xffffffffu, d1, 1);
            d0 += __shfl_xor_sync(0xffffffffu, d0, 2);
            d1 += __shfl_xor_sync(0xffffffffu, d1, 2);
            d0 += __shfl_xor_sync(0xffffffffu, d0, 4);
            d1 += __shfl_xor_sync(0xffffffffu, d1, 4);
            float a0 = d0 * pscale;
            float a1 = two ? d1 * pscale : -INFINITY;
            float mn = fmaxf(m, fmaxf(a0, a1));
            float sc = __expf(m - mn);
            float p0 = __expf(a0 - mn);
            float p1 = two ? __expf(a1 - mn) : 0.f;
            s = s * sc + p0 + p1;
            acc.x = acc.x * sc + p0 * va.x + p1 * vb2.x;
            acc.y = acc.y * sc + p0 * va.y + p1 * vb2.y;
            acc.z = acc.z * sc + p0 * va.z + p1 * vb2.z;
            acc.w = acc.w * sc + p0 * va.w + p1 * vb2.w;
            m = mn;
            ka = kc; va = vc; kb2 = kd; vb2 = vd;
        }
        float inv = 1.f / (s + 1e-16f);
        tot.x += acc.x * inv; tot.y += acc.y * inv;
        tot.z += acc.z * inv; tot.w += acc.w * inv;
    }
    uint2 outv;
    outv.x = pk_h2(__float2half_rn(gelu_f(tot.x)), __float2half_rn(gelu_f(tot.y)));
    outv.y = pk_h2(__float2half_rn(gelu_f(tot.z)), __float2half_rn(gelu_f(tot.w)));
    *(uint2*)(agg + (size_t)w * CDIM + loff) = outv;
}

// ---------------- host orchestration -------------------------------------------
extern "C" void kernel_launch(void* const* d_in, const int* in_sizes, int n_in,
                              void* d_out, int out_size) {
    const float* x_paper  = (const float*)d_in[0];
    const float* x_author = (const float*)d_in[1];
    const float* lin_w = (const float*)d_in[2];
    const float* lin_b = (const float*)d_in[3];
    const float* k_w = (const float*)d_in[4];
    const float* k_b = (const float*)d_in[5];
    const float* q_w = (const float*)d_in[6];
    const float* q_b = (const float*)d_in[7];
    const float* v_w = (const float*)d_in[8];
    const float* v_b = (const float*)d_in[9];
    const float* a_w = (const float*)d_in[10];
    const float* a_b = (const float*)d_in[11];
    const float* skip  = (const float*)d_in[12];
    const float* a_rel = (const float*)d_in[13];
    const float* m_rel = (const float*)d_in[14];
    const float* p_rel = (const float*)d_in[15];
    const int* srcs[3] = {(const int*)d_in[16], (const int*)d_in[18], (const int*)d_in[20]};
    const int* dsts[3] = {(const int*)d_in[17], (const int*)d_in[19], (const int*)d_in[21]};
    int E[3] = {in_sizes[16], in_sizes[18], in_sizes[20]};

    static cudaStream_t s1 = nullptr;
    static cudaEvent_t ev[2];
    if (!s1) {
        cudaStreamCreateWithFlags(&s1, cudaStreamNonBlocking);
        for (int i = 0; i < 2; i++) cudaEventCreateWithFlags(&ev[i], cudaEventDisableTiming);
        cudaFuncSetAttribute(gemm_mega, cudaFuncAttributeMaxDynamicSharedMemorySize, SM_NEED);
    }
    cudaStream_t s0 = 0;

    void* p;
    float *xb[2], *Wk, *Wv, *bk, *bv;
    __half *qb, *krel, *vrel, *agg;
    uint32_t* wpack;
    int *rowptr[3], *csrc[3], *cnt, *bsum;
    cudaGetSymbolAddress(&p, g_x);    xb[0] = (float*)p; xb[1] = xb[0] + (size_t)(NP + NA) * CDIM;
    cudaGetSymbolAddress(&p, g_q);    qb    = (__half*)p;
    cudaGetSymbolAddress(&p, g_krel); krel  = (__half*)p;
    cudaGetSymbolAddress(&p, g_vrel); vrel  = (__half*)p;
    cudaGetSymbolAddress(&p, g_agg);  agg   = (__half*)p;
    cudaGetSymbolAddress(&p, g_Wk);   Wk    = (float*)p;
    cudaGetSymbolAddress(&p, g_Wv);   Wv    = (float*)p;
    cudaGetSymbolAddress(&p, g_bk);   bk    = (float*)p;
    cudaGetSymbolAddress(&p, g_bv);   bv    = (float*)p;
    cudaGetSymbolAddress(&p, g_wpack);wpack = (uint32_t*)p;
    cudaGetSymbolAddress(&p, g_rowptr);
    for (int r = 0; r < 3; r++) rowptr[r] = (int*)p + (size_t)r * (NP + 1);
    cudaGetSymbolAddress(&p, g_csrc);
    for (int r = 0; r < 3; r++) csrc[r] = (int*)p + (size_t)r * EMAX;
    cudaGetSymbolAddress(&p, g_cnt);  cnt  = (int*)p;
    cudaGetSymbolAddress(&p, g_bsum); bsum = (int*)p;

    auto slot = [&](int s) { return (const uint4*)(wpack + (size_t)s * SLOT_U32); };
    auto setKV = [&](GemmSeg& G, int t, int sl, const float* bias, void* out) {
        G.wp[t] = slot(sl); G.bias[t] = bias; G.out[t] = out;
        G.outHalf[t] = 1; G.eop[t] = 0;
    };

    // ==== fork s1 from capture-origin stream ====
    cudaEventRecord(ev[0], s0);
    cudaStreamWaitEvent(s1, ev[0], 0);

    // launch order: build_comp(1), pack(2), fill_i(3), mega0(4)
    build_comp<<<dim3(CDIM, 3, 2), CDIM, 0, s0>>>(k_w, k_b, v_w, v_b, a_rel, m_rel,
                                                  Wk, bk, Wv, bv);
    {
        PackSrc ps{};
        for (int l = 0; l < 2; l++) {
            int base = l * 10;
            ps.w[base + 0] = q_w + (size_t)(l * 2 + 0) * CC;
            ps.w[base + 1] = q_w + (size_t)(l * 2 + 1) * CC;
            ps.w[base + 2] = Wk + (size_t)(l * 3 + 0) * CC;
            ps.w[base + 3] = Wv + (size_t)(l * 3 + 0) * CC;
            ps.w[base + 4] = Wk + (size_t)(l * 3 + 2) * CC;
            ps.w[base + 5] = Wv + (size_t)(l * 3 + 2) * CC;
            ps.w[base + 6] = Wk + (size_t)(l * 3 + 1) * CC;
            ps.w[base + 7] = Wv + (size_t)(l * 3 + 1) * CC;
            ps.w[base + 8] = a_w + (size_t)(l * 2 + 0) * CC;
            ps.w[base + 9] = a_w + (size_t)(l * 2 + 1) * CC;
        }
        ps.w[20] = lin_w; ps.w[21] = lin_w + CC;
        ps.count = NSLOT;
        pack_weights<<<dim3(NSLOT, 8), 128, 0, s0>>>(ps, wpack);
    }
    fill_i<<<(NP + 255) / 256, 256, 0, s1>>>(cnt, 0, NP);

    // megaGEMM0: wrapper(relu) chained into L0 q/krel/vrel
    {
        GemmSeg P{}, Q{};
        const float* bk0 = bk;
        const float* bv0 = bv;
        P.A = x_paper; P.xold = nullptr; P.skipp = nullptr;
        P.M = NP; P.ntiles = 6; P.chain = 1; P.aHalf = 0;
        P.wp[0] = slot(20); P.bias[0] = lin_b; P.out[0] = xb[0]; P.outHalf[0] = 0; P.eop[0] = 1;
        setKV(P, 1, 0, q_b, qb);
        setKV(P, 2, 2, bk0,            krel);
        setKV(P, 3, 3, bv0,            vrel);
        setKV(P, 4, 4, bk0 + 2 * CDIM, krel + 2 * (size_t)NPC);
        setKV(P, 5, 5, bv0 + 2 * CDIM, vrel + 2 * (size_t)NPC);
        Q.A = x_author; Q.xold = nullptr; Q.skipp = nullptr;
        Q.M = NA; Q.ntiles = 4; Q.chain = 1; Q.aHalf = 0;
        Q.wp[0] = slot(21); Q.bias[0] = lin_b + CDIM; Q.out[0] = xb[0] + NPC; Q.outHalf[0] = 0; Q.eop[0] = 1;
        setKV(Q, 1, 1, q_b + CDIM, qb + NPC);
        setKV(Q, 2, 6, bk0 + CDIM, krel + (size_t)NPC);
        setKV(Q, 3, 7, bv0 + CDIM, vrel + (size_t)NPC);
        gemm_mega<<<CTAS_P + CTAS_A, 256, SM_NEED, s0>>>(P, Q, CTAS_P);
    }

    // rest of CSR build on s1 (concurrent with mega0)
    {
        int r = 0;
        int Nd = NP;
        hist_k<<<(E[r] + 255) / 256, 256, 0, s1>>>(dsts[r], cnt, E[r]);
        int nb = (Nd + 4095) / 4096;
        scan1<<<nb, 256, 0, s1>>>(cnt, rowptr[r] + 1, bsum, Nd);
        scan2<<<1, 32, 0, s1>>>(bsum, nb);
        scan3<<<(Nd + 255) / 256, 256, 0, s1>>>(rowptr[r], bsum, cnt, Nd);
        csr_fill<<<(E[r] + 255) / 256, 256, 0, s1>>>(srcs[r], dsts[r], cnt, csrc[r], E[r]);
    }
    for (int r = 1; r < 3; r++) {
        int Nd = (r == 2) ? NA : NP;
        fill_i<<<(Nd + 255) / 256, 256, 0, s1>>>(cnt, 0, Nd);
        hist_k<<<(E[r] + 255) / 256, 256, 0, s1>>>(dsts[r], cnt, E[r]);
        int nb = (Nd + 4095) / 4096;
        scan1<<<nb, 256, 0, s1>>>(cnt, rowptr[r] + 1, bsum, Nd);
        scan2<<<1, 32, 0, s1>>>(bsum, nb);
        scan3<<<(Nd + 255) / 256, 256, 0, s1>>>(rowptr[r], bsum, cnt, Nd);
        csr_fill<<<(E[r] + 255) / 256, 256, 0, s1>>>(srcs[r], dsts[r], cnt, csrc[r], E[r]);
    }
    cudaEventRecord(ev[1], s1);
    cudaStreamWaitEvent(s0, ev[1], 0);

    // gather L0
    gather_all<<<((NP + NA) * 32 + 255) / 256, 256, 0, s0>>>(
        qb, agg, krel, vrel,
        rowptr[0], csrc[0], rowptr[1], csrc[1], rowptr[2], csrc[2],
        p_rel + 0 * 3 * NH);

    // megaGEMM1
    {
        GemmSeg P{}, Q{};
        const float* bk1 = bk + 3 * CDIM;
        const float* bv1 = bv + 3 * CDIM;
        P.A = agg; P.xold = xb[0]; P.skipp = skip + 0;
        P.M = NP; P.ntiles = 6; P.chain = 1; P.aHalf = 1;
        P.wp[0] = slot(8);  P.bias[0] = a_b; P.out[0] = xb[1]; P.outHalf[0] = 0; P.eop[0] = 2;
        setKV(P, 1, 10, q_b + 2 * CDIM, qb);
        setKV(P, 2, 12, bk1,            krel);
        setKV(P, 3, 13, bv1,            vrel);
        setKV(P, 4, 14, bk1 + 2 * CDIM, krel + 2 * (size_t)NPC);
        setKV(P, 5, 15, bv1 + 2 * CDIM, vrel + 2 * (size_t)NPC);
        Q.A = agg + NPC; Q.xold = xb[0] + NPC; Q.skipp = skip + 1;
        Q.M = NA; Q.ntiles = 4; Q.chain = 1; Q.aHalf = 1;
        Q.wp[0] = slot(9); Q.bias[0] = a_b + CDIM; Q.out[0] = xb[1] + NPC; Q.outHalf[0] = 0; Q.eop[0] = 2;
        setKV(Q, 1, 11, q_b + 3 * CDIM, qb + NPC);
        setKV(Q, 2, 16, bk1 + CDIM, krel + (size_t)NPC);
        setKV(Q, 3, 17, bv1 + CDIM, vrel + (size_t)NPC);
        gemm_mega<<<CTAS_P + CTAS_A, 256, SM_NEED, s0>>>(P, Q, CTAS_P);
    }

    // gather L1
    gather_all<<<((NP + NA) * 32 + 255) / 256, 256, 0, s0>>>(
        qb, agg, krel, vrel,
        rowptr[0], csrc[0], rowptr[1], csrc[1], rowptr[2], csrc[2],
        p_rel + 1 * 3 * NH);

    // final: L1 out-proj -> d_out
    {
        GemmSeg P{}, Q{};
        P.A = agg; P.xold = xb[1]; P.skipp = skip + 2;
        P.M = NP; P.ntiles = 1; P.chain = 0; P.aHalf = 1;
        P.wp[0] = slot(18); P.bias[0] = a_b + 2 * CDIM; P.out[0] = (float*)d_out;
        P.outHalf[0] = 0; P.eop[0] = 2;
        Q.A = agg + NPC; Q.xold = xb[1] + NPC; Q.skipp = skip + 3;
        Q.M = NA; Q.ntiles = 1; Q.chain = 0; Q.aHalf = 1;
        Q.wp[0] = slot(19); Q.bias[0] = a_b + 3 * CDIM; Q.out[0] = (float*)d_out + NPC;
        Q.outHalf[0] = 0; Q.eop[0] = 2;
        gemm_mega<<<CTAS_P + CTAS_A, 256, SM_NEED, s0>>>(P, Q, CTAS_P);
    }
}

// round 15
// speedup vs baseline: 1.3222x; 1.0472x over previous
#include <cuda_runtime.h>
#include <cuda_fp16.h>
#include <math.h>
#include <stdint.h>

#define NP 100000
#define NA 50000
#define CDIM 128
#define CC (CDIM*CDIM)
#define NH 4
#define NPC (NP*CDIM)
#define EMAX 300000

#define PITCH 136                 // fp16 per row in staged images
#define PITCHB 272                // bytes
#define A_IMG 17408               // 64 rows * 272B
#define B_IMG 34816               // 128 rows * 272B
#define SLOT_U32 8704
#define NSLOT 22
#define CTAS_P ((NP+63)/64)
#define CTAS_A ((NA+63)/64)

// ---------------- scratch (device globals) -----------------------------------
__device__ float  g_x[2][(NP+NA)*CDIM];
__device__ __half g_q[(NP+NA)*CDIM];
__device__ __half g_krel[3][NPC];
__device__ __half g_vrel[3][NPC];
__device__ __half g_agg[(NP+NA)*CDIM];
__device__ float  g_Wk[2][3][CC];
__device__ float  g_Wv[2][3][CC];
__device__ float  g_bk[2][3][CDIM];
__device__ float  g_bv[2][3][CDIM];
__device__ uint32_t g_wpack[NSLOT][SLOT_U32];
__device__ int g_rowptr[3][NP+1];
__device__ int g_csrc[3][EMAX];
__device__ int g_cnt[NP];
__device__ int g_bsum[64];

// ---------------- small helpers ----------------------------------------------
__device__ __forceinline__ float gelu_f(float x) {
    return 0.5f * x * (1.0f + erff(x * 0.7071067811865476f));
}
__global__ void fill_i(int* __restrict__ p, int v, int n) {
    int i = blockIdx.x * blockDim.x + threadIdx.x;
    if (i < n) p[i] = v;
}
__global__ void hist_k(const int* __restrict__ dst, int* __restrict__ cnt, int E) {
    int i = blockIdx.x * blockDim.x + threadIdx.x;
    if (i < E) atomicAdd(&cnt[dst[i]], 1);
}
__global__ void scan1(const int* __restrict__ cnt, int* __restrict__ rp1,
                      int* __restrict__ bsum, int n) {
    __shared__ int sm[256];
    int base = blockIdx.x * 4096;
    int idx0 = base + threadIdx.x * 16;
    int v[16]; int t = 0;
#pragma unroll
    for (int j = 0; j < 16; j++) { int ix = idx0 + j; v[j] = (ix < n) ? cnt[ix] : 0; t += v[j]; }
    sm[threadIdx.x] = t;
    __syncthreads();
    for (int off = 1; off < 256; off <<= 1) {
        int x = 0;
        if ((int)threadIdx.x >= off) x = sm[threadIdx.x - off];
        __syncthreads();
        if ((int)threadIdx.x >= off) sm[threadIdx.x] += x;
        __syncthreads();
    }
    int run = sm[threadIdx.x] - t;
#pragma unroll
    for (int j = 0; j < 16; j++) { run += v[j]; int ix = idx0 + j; if (ix < n) rp1[ix] = run; }
    if (threadIdx.x == 255) bsum[blockIdx.x] = sm[255];
}
__global__ void scan2(int* __restrict__ bsum, int nb) {
    int tid = threadIdx.x;
    int orig = (tid < nb) ? bsum[tid] : 0;
    int v = orig;
    for (int off = 1; off < 32; off <<= 1) {
        int x = __shfl_up_sync(0xffffffffu, v, off);
        if (tid >= off) v += x;
    }
    if (tid < nb) bsum[tid] = v - orig;
}
__global__ void scan3(int* __restrict__ rowptr, const int* __restrict__ bsum,
                      int* __restrict__ cursor, int n) {
    int i = blockIdx.x * blockDim.x + threadIdx.x;
    if (i < n) {
        int val = rowptr[i + 1] + bsum[i >> 12];
        rowptr[i + 1] = val;
        if (i + 1 < n) cursor[i + 1] = val;
    }
    if (i == 0) { rowptr[0] = 0; cursor[0] = 0; }
}
__global__ void csr_fill(const int* __restrict__ src, const int* __restrict__ dst,
                         int* __restrict__ cursor, int* __restrict__ csrc, int E) {
    int i = blockIdx.x * blockDim.x + threadIdx.x;
    if (i >= E) return;
    int pos = atomicAdd(&cursor[dst[i]], 1);
    csrc[pos] = src[i];
}

// ---------------- PTX helpers -------------------------------------------------
__device__ __forceinline__ uint32_t smem_u32(const void* p) {
    uint32_t a;
    asm("{ .reg .u64 t; cvta.to.shared.u64 t, %1; cvt.u32.u64 %0, t; }" : "=r"(a) : "l"(p));
    return a;
}
__device__ __forceinline__ uint32_t pk_h2(__half a, __half b) {
    __half2 t = __halves2half2(a, b);
    return *reinterpret_cast<uint32_t*>(&t);
}
__device__ __forceinline__ void ldsm4(uint32_t* r, uint32_t addr) {
    asm volatile("ldmatrix.sync.aligned.m8n8.x4.shared.b16 {%0,%1,%2,%3}, [%4];"
        : "=r"(r[0]), "=r"(r[1]), "=r"(r[2]), "=r"(r[3]) : "r"(addr));
}
__device__ __forceinline__ void mma16816(float* c, const uint32_t* a, const uint32_t* b) {
    asm volatile("mma.sync.aligned.m16n8k16.row.col.f32.f16.f16.f32 "
        "{%0,%1,%2,%3}, {%4,%5,%6,%7}, {%8,%9}, {%0,%1,%2,%3};"
        : "+f"(c[0]), "+f"(c[1]), "+f"(c[2]), "+f"(c[3])
        : "r"(a[0]), "r"(a[1]), "r"(a[2]), "r"(a[3]), "r"(b[0]), "r"(b[1]));
}
__device__ __forceinline__ void cp16(uint32_t dst, const void* src) {
    asm volatile("cp.async.cg.shared.global [%0], [%1], 16;" :: "r"(dst), "l"(src));
}

// ---------------- weight packing: fp32 -> pitched fp16 -------------------------
struct PackSrc { const float* w[NSLOT]; int count; };
__global__ void pack_weights(PackSrc ps, uint32_t* dstbase) {
    int m = blockIdx.x;
    if (m >= ps.count) return;
    const float* W = ps.w[m];
    uint32_t* hi = dstbase + (size_t)m * SLOT_U32;
    int n = threadIdx.x;
    int k0 = blockIdx.y * 16;
    for (int k = k0; k < k0 + 16; k += 2) {
        hi[n * (PITCH / 2) + (k >> 1)] =
            pk_h2(__float2half_rn(W[k * 128 + n]), __float2half_rn(W[(k + 1) * 128 + n]));
    }
}

// ---------------- composite relation weights (both layers) ---------------------
__global__ void build_comp(const float* __restrict__ kw0, const float* __restrict__ kb0,
                           const float* __restrict__ vw0, const float* __restrict__ vb0,
                           const float* __restrict__ arel0, const float* __restrict__ mrel0,
                           float* __restrict__ Wk0, float* __restrict__ bk0,
                           float* __restrict__ Wv0, float* __restrict__ bv0) {
    int c = blockIdx.x, r = blockIdx.y, l = blockIdx.z, j = threadIdx.x;
    const float* kw = kw0 + (size_t)l * 2 * CC;
    const float* kb = kb0 + l * 2 * CDIM;
    const float* vw = vw0 + (size_t)l * 2 * CC;
    const float* vb = vb0 + l * 2 * CDIM;
    const float* arel = arel0 + (size_t)l * 3 * NH * 1024;
    const float* mrel = mrel0 + (size_t)l * 3 * NH * 1024;
    float* Wk = Wk0 + (size_t)l * 3 * CC;
    float* Wv = Wv0 + (size_t)l * 3 * CC;
    float* bk = bk0 + l * 3 * CDIM;
    float* bv = bv0 + l * 3 * CDIM;
    int st = (r == 1) ? 1 : 0;
    int h = j >> 5, e = j & 31;
    const float* kwp = kw + ((size_t)st * CDIM + c) * CDIM + h * 32;
    const float* vwp = vw + ((size_t)st * CDIM + c) * CDIM + h * 32;
    const float* ap  = arel + (size_t)(r * NH + h) * 1024 + e;
    const float* mp  = mrel + (size_t)(r * NH + h) * 1024 + e;
    float sk = 0.f, sv = 0.f;
#pragma unroll
    for (int d = 0; d < 32; d++) {
        sk += kwp[d] * ap[d * 32];
        sv += vwp[d] * mp[d * 32];
    }
    Wk[(size_t)r * CC + (size_t)c * CDIM + j] = sk;
    Wv[(size_t)r * CC + (size_t)c * CDIM + j] = sv;
    if (c == 0) {
        float bks = 0.f, bvs = 0.f;
        const float* kbp = kb + st * CDIM + h * 32;
        const float* vbp = vb + st * CDIM + h * 32;
#pragma unroll
        for (int d = 0; d < 32; d++) {
            bks += kbp[d] * ap[d * 32];
            bvs += vbp[d] * mp[d * 32];
        }
        bk[r * CDIM + j] = bks;
        bv[r * CDIM + j] = bvs;
    }
}

// ---------------- segmented chained mega-GEMM (3 CTA/SM, single B buffer) ------
struct GemmSeg {
    const void*  A;
    const float* xold;
    const float* skipp;
    int M;
    int ntiles;
    int chain;
    int aHalf;
    const uint4* wp[6];
    const float* bias[6];
    void*        out[6];
    int          outHalf[6];
    int          eop[6];
};

#define SM_A    0
#define SM_BUF  A_IMG
#define SM_SCR  (A_IMG + B_IMG)
#define SM_NEED (A_IMG + B_IMG + A_IMG)   // 69632 bytes -> 3 CTAs/SM

__device__ __forceinline__ void prefetch_B(uint32_t dstb, const uint4* src, int tid) {
#pragma unroll
    for (int i = 0; i < 8; i++) cp16(dstb + (uint32_t)(i * 256 + tid) * 16, src + i * 256 + tid);
    if (tid < 128) cp16(dstb + (uint32_t)(2048 + tid) * 16, src + 2048 + tid);
    asm volatile("cp.async.commit_group;" ::: "memory");
}

__global__ void __launch_bounds__(256, 3)
gemm_mega(GemmSeg P0, GemmSeg P1, int ctas0) {
    extern __shared__ char sm[];
    uint32_t sb = smem_u32(sm);
    int tid = threadIdx.x, lane = tid & 31, wid = tid >> 5;
    int wm = wid & 1, wn = wid >> 1;
    int bx = blockIdx.x;
    bool seg1 = bx >= ctas0;
    const GemmSeg& P = seg1 ? P1 : P0;
    int rowBase = (seg1 ? bx - ctas0 : bx) * 64;
    int M = P.M;

    prefetch_B(sb + SM_BUF, P.wp[0], tid);

    // ---- stage A ----
    if (P.aHalf) {
        const __half* Ah = (const __half*)P.A;
#pragma unroll
        for (int it = 0; it < 4; it++) {
            int f = it * 256 + tid;
            int m = f >> 4, c = f & 15;
            int row = rowBase + m;
            uint4 v = make_uint4(0, 0, 0, 0);
            if (row < M) v = *(const uint4*)(Ah + (size_t)row * CDIM + c * 8);
            *(uint4*)(sm + SM_A + m * PITCHB + c * 16) = v;
        }
    } else {
        const float* Af = (const float*)P.A;
#pragma unroll 4
        for (int it = 0; it < 8; it++) {
            int f = it * 256 + tid;
            int m = f >> 5, k = (f & 31) << 2;
            int row = rowBase + m;
            float4 v = make_float4(0.f, 0.f, 0.f, 0.f);
            if (row < M) v = *(const float4*)(Af + (size_t)row * CDIM + k);
            uint32_t off = (uint32_t)(m * PITCHB + k * 2);
            *(uint2*)(sm + SM_A + off) = make_uint2(
                pk_h2(__float2half_rn(v.x), __float2half_rn(v.y)),
                pk_h2(__float2half_rn(v.z), __float2half_rn(v.w)));
        }
    }

    int aRow = wm * 32 + (lane & 15);
    uint32_t aKoff = (lane & 16) ? 16u : 0u;
    uint32_t aBase = sb + SM_A + aRow * PITCHB + aKoff;
    int bN = wn * 32 + (lane & 7) + ((lane & 16) ? 8 : 0);
    uint32_t bKoff = (lane & 8) ? 16u : 0u;
    uint32_t bOff = bN * PITCHB + bKoff;

    float skv = 0.f;
    if (P.skipp) skv = 1.f / (1.f + expf(-*P.skipp));
    int g = lane >> 2, tg = lane & 3;
    int nt = P.ntiles;

    for (int b = 0; b < nt; b++) {
        asm volatile("cp.async.wait_group 0;" ::: "memory");
        __syncthreads();   // B ready; prior epilogue/chain/scratch done

        float acc[2][4][4];
#pragma unroll
        for (int i = 0; i < 2; i++)
#pragma unroll
            for (int j = 0; j < 4; j++)
#pragma unroll
                for (int q = 0; q < 4; q++) acc[i][j][q] = 0.f;

        uint32_t aCur = aBase, bHi = sb + SM_BUF + bOff;
#pragma unroll
        for (int ks = 0; ks < 8; ks++) {
            uint32_t ah[2][4], bh[2][4];
            ldsm4(ah[0], aCur); ldsm4(ah[1], aCur + 16 * PITCHB);
            ldsm4(bh[0], bHi);  ldsm4(bh[1], bHi + 16 * PITCHB);
#pragma unroll
            for (int i = 0; i < 2; i++)
#pragma unroll
                for (int j = 0; j < 4; j++)
                    mma16816(acc[i][j], ah[i], &bh[j >> 1][(j & 1) * 2]);
            aCur += 32; bHi += 32;
        }
        __syncthreads();   // all B reads done -> safe to overwrite with prefetch

        // prefetch next tile's B, overlapping the epilogue
        if (b + 1 < nt) prefetch_B(sb + SM_BUF, P.wp[b + 1], tid);

        const float* bias = P.bias[b];
        int eop = P.eop[b];
        int oh = P.outHalf[b];
        bool chain0 = (b == 0) && P.chain;

        if (oh && eop == 0 && !chain0) {
            // ---- fast path: transpose via dedicated scratch, coalesced stores
            __half* outH = (__half*)P.out[b];
            char* scr = sm + SM_SCR;
#pragma unroll
            for (int i = 0; i < 2; i++)
#pragma unroll
                for (int j = 0; j < 4; j++) {
                    int col = wn * 32 + j * 8 + tg * 2;
                    float b0 = bias[col], b1 = bias[col + 1];
#pragma unroll
                    for (int half = 0; half < 2; half++) {
                        int rl = wm * 32 + i * 16 + half * 8 + g;
                        float v0 = acc[i][j][half * 2 + 0] + b0;
                        float v1 = acc[i][j][half * 2 + 1] + b1;
                        *(uint32_t*)(scr + rl * PITCHB + col * 2) =
                            pk_h2(__float2half_rn(v0), __float2half_rn(v1));
                    }
                }
            __syncthreads();
#pragma unroll
            for (int it = 0; it < 4; it++) {
                int f = it * 256 + tid;
                int m = f >> 4, c = f & 15;
                int row = rowBase + m;
                uint4 v = *(uint4*)(scr + m * PITCHB + c * 16);
                if (row < M)
                    *(uint4*)(outH + (size_t)row * CDIM + c * 8) = v;
            }
        } else {
            // ---- general path (fp32 out / relu / skip-blend / chain) ----
            float* outF = (float*)P.out[b];
            __half* outH = (__half*)P.out[b];
#pragma unroll
            for (int i = 0; i < 2; i++) {
                int r0 = rowBase + wm * 32 + i * 16 + g;
#pragma unroll
                for (int j = 0; j < 4; j++) {
                    int col = wn * 32 + j * 8 + tg * 2;
                    float b0 = bias[col], b1 = bias[col + 1];
#pragma unroll
                    for (int half = 0; half < 2; half++) {
                        int row = r0 + half * 8;
                        if (row >= M) continue;
                        float v0 = acc[i][j][half * 2 + 0] + b0;
                        float v1 = acc[i][j][half * 2 + 1] + b1;
                        if (eop == 1) {
                            v0 = fmaxf(v0, 0.f); v1 = fmaxf(v1, 0.f);
                        } else if (eop == 2) {
                            float2 xo = *(const float2*)(P.xold + (size_t)row * CDIM + col);
                            v0 = skv * v0 + (1.f - skv) * xo.x;
                            v1 = skv * v1 + (1.f - skv) * xo.y;
                        }
                        if (oh) {
                            *(__half2*)(outH + (size_t)row * CDIM + col) = __floats2half2_rn(v0, v1);
                        } else {
                            *(float2*)(outF + (size_t)row * CDIM + col) = make_float2(v0, v1);
                        }
                        if (chain0) {
                            uint32_t off = (uint32_t)((row - rowBase) * PITCHB + col * 2);
                            *(__half2*)(sm + SM_A + off) = __floats2half2_rn(v0, v1);
                        }
                    }
                }
            }
        }
    }
}

// ---------------- merged edge gather: pair-unrolled, fp16 q/k/v ---------------
__device__ __forceinline__ float4 ld_half4(const __half* base, size_t off) {
    uint2 raw = *(const uint2*)(base + off);
    __half2* ph = (__half2*)&raw;
    float2 a = __half22float2(ph[0]);
    float2 b = __half22float2(ph[1]);
    return make_float4(a.x, a.y, b.x, b.y);
}
__device__ __forceinline__ float dot4(float4 a, float4 b) {
    return a.x * b.x + a.y * b.y + a.z * b.z + a.w * b.w;
}

__global__ void __launch_bounds__(256)
gather_all(const __half* __restrict__ q, __half* __restrict__ agg,
           const __half* __restrict__ krel, const __half* __restrict__ vrel,
           const int* __restrict__ rp0, const int* __restrict__ cs0,
           const int* __restrict__ rp1, const int* __restrict__ cs1,
           const int* __restrict__ rp2, const int* __restrict__ cs2,
           const float* __restrict__ prel) {
    int w = (blockIdx.x * blockDim.x + threadIdx.x) >> 5;
    if (w >= NP + NA) return;
    int lane = threadIdx.x & 31;
    int h = lane >> 3;
    size_t loff = (size_t)lane * 4;
    float4 qv = ld_half4(q, (size_t)w * CDIM + loff);
    float4 tot = make_float4(0.f, 0.f, 0.f, 0.f);
    int nrel, node;
    const int* rps[2]; const int* css[2]; int rr[2];
    if (w < NP) {
        nrel = 2; node = w;
        rps[0] = rp0; css[0] = cs0; rr[0] = 0;
        rps[1] = rp1; css[1] = cs1; rr[1] = 1;
    } else {
        nrel = 1; node = w - NP;
        rps[0] = rp2; css[0] = cs2; rr[0] = 2;
        rps[1] = rp2; css[1] = cs2; rr[1] = 2;
    }
    for (int rel = 0; rel < nrel; rel++) {
        const __half* kr = krel + (size_t)rr[rel] * NPC;
        const __half* vr = vrel + (size_t)rr[rel] * NPC;
        const int* rp = rps[rel];
        const int* cs = css[rel];
        float pscale = prel[rr[rel] * NH + h] * 0.17677669529663687f;
        int beg = rp[node], end = rp[node + 1];
        float m = -INFINITY, s = 0.f;
        float4 acc = make_float4(0.f, 0.f, 0.f, 0.f);

        float4 ka, va, kb2, vb2;
        if (beg < end) {
            int s0 = cs[beg];
            int s1 = (beg + 1 < end) ? cs[beg + 1] : s0;
            ka  = ld_half4(kr, (size_t)s0 * CDIM + loff);
            va  = ld_half4(vr, (size_t)s0 * CDIM + loff);
            kb2 = ld_half4(kr, (size_t)s1 * CDIM + loff);
            vb2 = ld_half4(vr, (size_t)s1 * CDIM + loff);
        }
        for (int e = beg; e < end; e += 2) {
            bool two = (e + 1 < end);
            float4 kc, vc, kd, vd;
            if (e + 2 < end) {
                int s0 = cs[e + 2];
                int s1 = (e + 3 < end) ? cs[e + 3] : s0;
                kc = ld_half4(kr, (size_t)s0 * CDIM + loff);
                vc = ld_half4(vr, (size_t)s0 * CDIM + loff);
                kd = ld_half4(kr, (size_t)s1 * CDIM + loff);
                vd = ld_half4(vr, (size_t)s1 * CDIM + loff);
            }
            float d0 = dot4(qv, ka);
            float d1 = dot4(qv, kb2);
            d0 += __shfl_xor_sync(0xffffffffu, d0, 1);
            d1 += __shfl_xor_sync(0xffffffffu, d1, 1);
            d0 += __shfl_xor_sync(0xffffffffu, d0, 2);
            d1 += __shfl_xor_sync(0xffffffffu, d1, 2);
            d0 += __shfl_xor_sync(0xffffffffu, d0, 4);
            d1 += __shfl_xor_sync(0xffffffffu, d1, 4);
            float a0 = d0 * pscale;
            float a1 = two ? d1 * pscale : -INFINITY;
            float mn = fmaxf(m, fmaxf(a0, a1));
            float sc = __expf(m - mn);
            float p0 = __expf(a0 - mn);
            float p1 = two ? __expf(a1 - mn) : 0.f;
            s = s * sc + p0 + p1;
            acc.x = acc.x * sc + p0 * va.x + p1 * vb2.x;
            acc.y = acc.y * sc + p0 * va.y + p1 * vb2.y;
            acc.z = acc.z * sc + p0 * va.z + p1 * vb2.z;
            acc.w = acc.w * sc + p0 * va.w + p1 * vb2.w;
            m = mn;
            ka = kc; va = vc; kb2 = kd; vb2 = vd;
        }
        float inv = 1.f / (s + 1e-16f);
        tot.x += acc.x * inv; tot.y += acc.y * inv;
        tot.z += acc.z * inv; tot.w += acc.w * inv;
    }
    uint2 outv;
    outv.x = pk_h2(__float2half_rn(gelu_f(tot.x)), __float2half_rn(gelu_f(tot.y)));
    outv.y = pk_h2(__float2half_rn(gelu_f(tot.z)), __float2half_rn(gelu_f(tot.w)));
    *(uint2*)(agg + (size_t)w * CDIM + loff) = outv;
}

// ---------------- host orchestration -------------------------------------------
extern "C" void kernel_launch(void* const* d_in, const int* in_sizes, int n_in,
                              void* d_out, int out_size) {
    const float* x_paper  = (const float*)d_in[0];
    const float* x_author = (const float*)d_in[1];
    const float* lin_w = (const float*)d_in[2];
    const float* lin_b = (const float*)d_in[3];
    const float* k_w = (const float*)d_in[4];
    const float* k_b = (const float*)d_in[5];
    const float* q_w = (const float*)d_in[6];
    const float* q_b = (const float*)d_in[7];
    const float* v_w = (const float*)d_in[8];
    const float* v_b = (const float*)d_in[9];
    const float* a_w = (const float*)d_in[10];
    const float* a_b = (const float*)d_in[11];
    const float* skip  = (const float*)d_in[12];
    const float* a_rel = (const float*)d_in[13];
    const float* m_rel = (const float*)d_in[14];
    const float* p_rel = (const float*)d_in[15];
    const int* srcs[3] = {(const int*)d_in[16], (const int*)d_in[18], (const int*)d_in[20]};
    const int* dsts[3] = {(const int*)d_in[17], (const int*)d_in[19], (const int*)d_in[21]};
    int E[3] = {in_sizes[16], in_sizes[18], in_sizes[20]};

    static cudaStream_t s1 = nullptr;
    static cudaEvent_t ev[2];
    if (!s1) {
        cudaStreamCreateWithFlags(&s1, cudaStreamNonBlocking);
        for (int i = 0; i < 2; i++) cudaEventCreateWithFlags(&ev[i], cudaEventDisableTiming);
        cudaFuncSetAttribute(gemm_mega, cudaFuncAttributeMaxDynamicSharedMemorySize, SM_NEED);
    }
    cudaStream_t s0 = 0;

    void* p;
    float *xb[2], *Wk, *Wv, *bk, *bv;
    __half *qb, *krel, *vrel, *agg;
    uint32_t* wpack;
    int *rowptr[3], *csrc[3], *cnt, *bsum;
    cudaGetSymbolAddress(&p, g_x);    xb[0] = (float*)p; xb[1] = xb[0] + (size_t)(NP + NA) * CDIM;
    cudaGetSymbolAddress(&p, g_q);    qb    = (__half*)p;
    cudaGetSymbolAddress(&p, g_krel); krel  = (__half*)p;
    cudaGetSymbolAddress(&p, g_vrel); vrel  = (__half*)p;
    cudaGetSymbolAddress(&p, g_agg);  agg   = (__half*)p;
    cudaGetSymbolAddress(&p, g_Wk);   Wk    = (float*)p;
    cudaGetSymbolAddress(&p, g_Wv);   Wv    = (float*)p;
    cudaGetSymbolAddress(&p, g_bk);   bk    = (float*)p;
    cudaGetSymbolAddress(&p, g_bv);   bv    = (float*)p;
    cudaGetSymbolAddress(&p, g_wpack);wpack = (uint32_t*)p;
    cudaGetSymbolAddress(&p, g_rowptr);
    for (int r = 0; r < 3; r++) rowptr[r] = (int*)p + (size_t)r * (NP + 1);
    cudaGetSymbolAddress(&p, g_csrc);
    for (int r = 0; r < 3; r++) csrc[r] = (int*)p + (size_t)r * EMAX;
    cudaGetSymbolAddress(&p, g_cnt);  cnt  = (int*)p;
    cudaGetSymbolAddress(&p, g_bsum); bsum = (int*)p;

    auto slot = [&](int s) { return (const uint4*)(wpack + (size_t)s * SLOT_U32); };
    auto setKV = [&](GemmSeg& G, int t, int sl, const float* bias, void* out) {
        G.wp[t] = slot(sl); G.bias[t] = bias; G.out[t] = out;
        G.outHalf[t] = 1; G.eop[t] = 0;
    };

    // ==== fork s1 from capture-origin stream ====
    cudaEventRecord(ev[0], s0);
    cudaStreamWaitEvent(s1, ev[0], 0);

    // launch order: build_comp(1), pack(2), fill_i(3), mega0(4)
    build_comp<<<dim3(CDIM, 3, 2), CDIM, 0, s0>>>(k_w, k_b, v_w, v_b, a_rel, m_rel,
                                                  Wk, bk, Wv, bv);
    {
        PackSrc ps{};
        for (int l = 0; l < 2; l++) {
            int base = l * 10;
            ps.w[base + 0] = q_w + (size_t)(l * 2 + 0) * CC;
            ps.w[base + 1] = q_w + (size_t)(l * 2 + 1) * CC;
            ps.w[base + 2] = Wk + (size_t)(l * 3 + 0) * CC;
            ps.w[base + 3] = Wv + (size_t)(l * 3 + 0) * CC;
            ps.w[base + 4] = Wk + (size_t)(l * 3 + 2) * CC;
            ps.w[base + 5] = Wv + (size_t)(l * 3 + 2) * CC;
            ps.w[base + 6] = Wk + (size_t)(l * 3 + 1) * CC;
            ps.w[base + 7] = Wv + (size_t)(l * 3 + 1) * CC;
            ps.w[base + 8] = a_w + (size_t)(l * 2 + 0) * CC;
            ps.w[base + 9] = a_w + (size_t)(l * 2 + 1) * CC;
        }
        ps.w[20] = lin_w; ps.w[21] = lin_w + CC;
        ps.count = NSLOT;
        pack_weights<<<dim3(NSLOT, 8), 128, 0, s0>>>(ps, wpack);
    }
    fill_i<<<(NP + 255) / 256, 256, 0, s1>>>(cnt, 0, NP);

    // megaGEMM0: wrapper(relu) chained into L0 q/krel/vrel
    {
        GemmSeg P{}, Q{};
        const float* bk0 = bk;
        const float* bv0 = bv;
        P.A = x_paper; P.xold = nullptr; P.skipp = nullptr;
        P.M = NP; P.ntiles = 6; P.chain = 1; P.aHalf = 0;
        P.wp[0] = slot(20); P.bias[0] = lin_b; P.out[0] = xb[0]; P.outHalf[0] = 0; P.eop[0] = 1;
        setKV(P, 1, 0, q_b, qb);
        setKV(P, 2, 2, bk0,            krel);
        setKV(P, 3, 3, bv0,            vrel);
        setKV(P, 4, 4, bk0 + 2 * CDIM, krel + 2 * (size_t)NPC);
        setKV(P, 5, 5, bv0 + 2 * CDIM, vrel + 2 * (size_t)NPC);
        Q.A = x_author; Q.xold = nullptr; Q.skipp = nullptr;
        Q.M = NA; Q.ntiles = 4; Q.chain = 1; Q.aHalf = 0;
        Q.wp[0] = slot(21); Q.bias[0] = lin_b + CDIM; Q.out[0] = xb[0] + NPC; Q.outHalf[0] = 0; Q.eop[0] = 1;
        setKV(Q, 1, 1, q_b + CDIM, qb + NPC);
        setKV(Q, 2, 6, bk0 + CDIM, krel + (size_t)NPC);
        setKV(Q, 3, 7, bv0 + CDIM, vrel + (size_t)NPC);
        gemm_mega<<<CTAS_P + CTAS_A, 256, SM_NEED, s0>>>(P, Q, CTAS_P);
    }

    // rest of CSR build on s1 (concurrent with mega0)
    {
        int r = 0;
        int Nd = NP;
        hist_k<<<(E[r] + 255) / 256, 256, 0, s1>>>(dsts[r], cnt, E[r]);
        int nb = (Nd + 4095) / 4096;
        scan1<<<nb, 256, 0, s1>>>(cnt, rowptr[r] + 1, bsum, Nd);
        scan2<<<1, 32, 0, s1>>>(bsum, nb);
        scan3<<<(Nd + 255) / 256, 256, 0, s1>>>(rowptr[r], bsum, cnt, Nd);
        csr_fill<<<(E[r] + 255) / 256, 256, 0, s1>>>(srcs[r], dsts[r], cnt, csrc[r], E[r]);
    }
    for (int r = 1; r < 3; r++) {
        int Nd = (r == 2) ? NA : NP;
        fill_i<<<(Nd + 255) / 256, 256, 0, s1>>>(cnt, 0, Nd);
        hist_k<<<(E[r] + 255) / 256, 256, 0, s1>>>(dsts[r], cnt, E[r]);
        int nb = (Nd + 4095) / 4096;
        scan1<<<nb, 256, 0, s1>>>(cnt, rowptr[r] + 1, bsum, Nd);
        scan2<<<1, 32, 0, s1>>>(bsum, nb);
        scan3<<<(Nd + 255) / 256, 256, 0, s1>>>(rowptr[r], bsum, cnt, Nd);
        csr_fill<<<(E[r] + 255) / 256, 256, 0, s1>>>(srcs[r], dsts[r], cnt, csrc[r], E[r]);
    }
    cudaEventRecord(ev[1], s1);
    cudaStreamWaitEvent(s0, ev[1], 0);

    // gather L0
    gather_all<<<((NP + NA) * 32 + 255) / 256, 256, 0, s0>>>(
        qb, agg, krel, vrel,
        rowptr[0], csrc[0], rowptr[1], csrc[1], rowptr[2], csrc[2],
        p_rel + 0 * 3 * NH);

    // megaGEMM1
    {
        GemmSeg P{}, Q{};
        const float* bk1 = bk + 3 * CDIM;
        const float* bv1 = bv + 3 * CDIM;
        P.A = agg; P.xold = xb[0]; P.skipp = skip + 0;
        P.M = NP; P.ntiles = 6; P.chain = 1; P.aHalf = 1;
        P.wp[0] = slot(8);  P.bias[0] = a_b; P.out[0] = xb[1]; P.outHalf[0] = 0; P.eop[0] = 2;
        setKV(P, 1, 10, q_b + 2 * CDIM, qb);
        setKV(P, 2, 12, bk1,            krel);
        setKV(P, 3, 13, bv1,            vrel);
        setKV(P, 4, 14, bk1 + 2 * CDIM, krel + 2 * (size_t)NPC);
        setKV(P, 5, 15, bv1 + 2 * CDIM, vrel + 2 * (size_t)NPC);
        Q.A = agg + NPC; Q.xold = xb[0] + NPC; Q.skipp = skip + 1;
        Q.M = NA; Q.ntiles = 4; Q.chain = 1; Q.aHalf = 1;
        Q.wp[0] = slot(9); Q.bias[0] = a_b + CDIM; Q.out[0] = xb[1] + NPC; Q.outHalf[0] = 0; Q.eop[0] = 2;
        setKV(Q, 1, 11, q_b + 3 * CDIM, qb + NPC);
        setKV(Q, 2, 16, bk1 + CDIM, krel + (size_t)NPC);
        setKV(Q, 3, 17, bv1 + CDIM, vrel + (size_t)NPC);
        gemm_mega<<<CTAS_P + CTAS_A, 256, SM_NEED, s0>>>(P, Q, CTAS_P);
    }

    // gather L1
    gather_all<<<((NP + NA) * 32 + 255) / 256, 256, 0, s0>>>(
        qb, agg, krel, vrel,
        rowptr[0], csrc[0], rowptr[1], csrc[1], rowptr[2], csrc[2],
        p_rel + 1 * 3 * NH);

    // final: L1 out-proj -> d_out
    {
        GemmSeg P{}, Q{};
        P.A = agg; P.xold = xb[1]; P.skipp = skip + 2;
        P.M = NP; P.ntiles = 1; P.chain = 0; P.aHalf = 1;
        P.wp[0] = slot(18); P.bias[0] = a_b + 2 * CDIM; P.out[0] = (float*)d_out;
        P.outHalf[0] = 0; P.eop[0] = 2;
        Q.A = agg + NPC; Q.xold = xb[1] + NPC; Q.skipp = skip + 3;
        Q.M = NA; Q.ntiles = 1; Q.chain = 0; Q.aHalf = 1;
        Q.wp[0] = slot(19); Q.bias[0] = a_b + 3 * CDIM; Q.out[0] = (float*)d_out + NPC;
        Q.outHalf[0] = 0; Q.eop[0] = 2;
        gemm_mega<<<CTAS_P + CTAS_A, 256, SM_NEED, s0>>>(P, Q, CTAS_P);
    }
}